// round 1
// baseline (speedup 1.0000x reference)
#include <cuda_runtime.h>
#include <cuda_bf16.h>
#include <math.h>

#define B_   2
#define S_   2048
#define HID_ 1024
#define NH_  16
#define HD_  64
#define M_   (B_ * S_)        // 4096
#define QKV_N (3 * HID_)      // 3072

// ---------------- scratch (device globals; no allocation allowed) ----------
__device__ float g_qkv[M_ * QKV_N];            // 4096 x 3072
__device__ float g_q[B_ * NH_ * S_ * HD_];     // [b,h,s,d]
__device__ float g_k[B_ * NH_ * S_ * HD_];
__device__ float g_v[B_ * NH_ * S_ * HD_];
__device__ float g_attno[M_ * HID_];           // [b,s,(h,d)] = [4096,1024]
__device__ float g_cos[S_ * HD_];
__device__ float g_sin[S_ * HD_];

// ---------------- RoPE tables (double precision trig -> f32) ---------------
__global__ void rope_table_kernel() {
    int idx = blockIdx.x * blockDim.x + threadIdx.x;
    if (idx >= S_ * HD_) return;
    int s = idx >> 6;
    int d = idx & 63;
    int i = d & 31;
    double inv = pow(10000.0, -((double)(2 * i)) / (double)HD_);
    float freq = (float)s * (float)inv;      // mimic f32 rounding of reference
    g_cos[idx] = (float)cos((double)freq);
    g_sin[idx] = (float)sin((double)freq);
}

// ---------------- generic fp32 GEMM: C[M,N] = A[M,K] @ W[K,N] (+bias) ------
// 128x128 block tile, BK=16, 256 threads, 8x8 micro-tile.
__global__ __launch_bounds__(256)
void gemm_kernel(const float* __restrict__ A, const float* __restrict__ W,
                 const float* __restrict__ bias, float* __restrict__ C,
                 int M, int N, int K) {
    __shared__ float As[16][132];   // transposed A tile: As[k][m]
    __shared__ float Bs[16][132];

    int tid  = threadIdx.x;
    int row0 = blockIdx.y * 128;
    int col0 = blockIdx.x * 128;
    int ty = tid >> 4;       // 0..15
    int tx = tid & 15;       // 0..15

    float acc[8][8];
#pragma unroll
    for (int i = 0; i < 8; i++)
#pragma unroll
        for (int j = 0; j < 8; j++) acc[i][j] = 0.0f;

    for (int k0 = 0; k0 < K; k0 += 16) {
        // load A 128x16 -> transposed
#pragma unroll
        for (int r = 0; r < 2; r++) {
            int id = tid + r * 256;            // 0..511 float4 ids
            int m  = id >> 2;
            int k4 = (id & 3) * 4;
            float4 f = *(const float4*)&A[(size_t)(row0 + m) * K + k0 + k4];
            As[k4 + 0][m] = f.x;
            As[k4 + 1][m] = f.y;
            As[k4 + 2][m] = f.z;
            As[k4 + 3][m] = f.w;
        }
        // load B 16x128
#pragma unroll
        for (int r = 0; r < 2; r++) {
            int id = tid + r * 256;
            int kk = id >> 5;
            int n4 = (id & 31) * 4;
            *(float4*)&Bs[kk][n4] =
                *(const float4*)&W[(size_t)(k0 + kk) * N + col0 + n4];
        }
        __syncthreads();

#pragma unroll
        for (int kk = 0; kk < 16; kk++) {
            float a[8], b[8];
            *(float4*)&a[0] = *(float4*)&As[kk][ty * 8];
            *(float4*)&a[4] = *(float4*)&As[kk][ty * 8 + 4];
            *(float4*)&b[0] = *(float4*)&Bs[kk][tx * 8];
            *(float4*)&b[4] = *(float4*)&Bs[kk][tx * 8 + 4];
#pragma unroll
            for (int i = 0; i < 8; i++)
#pragma unroll
                for (int j = 0; j < 8; j++)
                    acc[i][j] += a[i] * b[j];
        }
        __syncthreads();
    }

#pragma unroll
    for (int i = 0; i < 8; i++) {
        int row = row0 + ty * 8 + i;
#pragma unroll
        for (int jb = 0; jb < 8; jb += 4) {
            int col = col0 + tx * 8 + jb;
            float4 r;
            r.x = acc[i][jb + 0];
            r.y = acc[i][jb + 1];
            r.z = acc[i][jb + 2];
            r.w = acc[i][jb + 3];
            if (bias) {
                r.x += bias[col + 0];
                r.y += bias[col + 1];
                r.z += bias[col + 2];
                r.w += bias[col + 3];
            }
            *(float4*)&C[(size_t)row * N + col] = r;
        }
    }
}

// ---------------- qkv -> q,k,v with RoPE, layout [b,h,s,d] ------------------
__global__ void qkv_transform_kernel() {
    int e = blockIdx.x * blockDim.x + threadIdx.x;
    if (e >= B_ * NH_ * S_ * HD_) return;
    int d = e & 63;
    int s = (e >> 6) & (S_ - 1);
    int h = (e >> 17) & (NH_ - 1);
    int b = e >> 21;

    size_t base = ((size_t)(b * S_ + s)) * QKV_N;
    int c  = h * HD_ + d;
    int dp = (d < 32) ? d + 32 : d - 32;
    int c2 = h * HD_ + dp;
    float sgn = (d < 32) ? -1.0f : 1.0f;

    float qr = g_qkv[base + c];
    float q2 = g_qkv[base + c2];
    float kr = g_qkv[base + HID_ + c];
    float k2 = g_qkv[base + HID_ + c2];
    float vr = g_qkv[base + 2 * HID_ + c];

    float cs = g_cos[s * HD_ + d];
    float sn = g_sin[s * HD_ + d];

    g_q[e] = qr * cs + sgn * q2 * sn;
    g_k[e] = kr * cs + sgn * k2 * sn;
    g_v[e] = vr;
}

// ---------------- causal flash attention, fp32 ------------------------------
// grid: (S/64 q-tiles, B*NH). block: 256 threads (16x16), 4x4 micro-tiles.
#define ATS 68   // padded smem row stride

__global__ __launch_bounds__(256)
void attn_kernel(float* __restrict__ Out) {
    extern __shared__ float sm[];
    float* Qs = sm;                    // [64][ATS]  Q[row][d]
    float* KP = sm + 64 * ATS;         // [64][ATS]  Kt[d][col], later P[row][col]
    float* Vs = sm + 2 * 64 * ATS;     // [64][ATS]  V[tok][d]

    int qt = blockIdx.x;
    int bh = blockIdx.y;
    int b  = bh >> 4;
    int h  = bh & 15;

    const float* Qb = g_q + (size_t)bh * S_ * HD_;
    const float* Kb = g_k + (size_t)bh * S_ * HD_;
    const float* Vb = g_v + (size_t)bh * S_ * HD_;

    int tid = threadIdx.x;
    int ty = tid >> 4;
    int tx = tid & 15;

    // load Q tile (64 x 64)
#pragma unroll
    for (int r = 0; r < 4; r++) {
        int id  = tid + r * 256;       // float4 ids 0..1023
        int row = id >> 4;
        int d4  = (id & 15) * 4;
        *(float4*)&Qs[row * ATS + d4] =
            *(const float4*)&Qb[(size_t)(qt * 64 + row) * HD_ + d4];
    }

    float o[4][4];
    float m[4], l[4];
#pragma unroll
    for (int i = 0; i < 4; i++) {
        m[i] = -1e30f; l[i] = 0.0f;
#pragma unroll
        for (int j = 0; j < 4; j++) o[i][j] = 0.0f;
    }

    for (int kt = 0; kt <= qt; kt++) {
        __syncthreads();   // previous iter readers done
        // load K tile transposed + V tile
#pragma unroll
        for (int r = 0; r < 4; r++) {
            int id  = tid + r * 256;
            int row = id >> 4;
            int d4  = (id & 15) * 4;
            float4 kf = *(const float4*)&Kb[(size_t)(kt * 64 + row) * HD_ + d4];
            KP[(d4 + 0) * ATS + row] = kf.x;
            KP[(d4 + 1) * ATS + row] = kf.y;
            KP[(d4 + 2) * ATS + row] = kf.z;
            KP[(d4 + 3) * ATS + row] = kf.w;
            *(float4*)&Vs[row * ATS + d4] =
                *(const float4*)&Vb[(size_t)(kt * 64 + row) * HD_ + d4];
        }
        __syncthreads();

        // S = Q @ K^T  (64x64 tile, thread owns 4 rows x 4 cols)
        float s[4][4];
#pragma unroll
        for (int i = 0; i < 4; i++)
#pragma unroll
            for (int j = 0; j < 4; j++) s[i][j] = 0.0f;

        for (int kk = 0; kk < 64; kk++) {
            float4 kv = *(float4*)&KP[kk * ATS + tx * 4];
#pragma unroll
            for (int i = 0; i < 4; i++) {
                float qv = Qs[(ty * 4 + i) * ATS + kk];
                s[i][0] += qv * kv.x;
                s[i][1] += qv * kv.y;
                s[i][2] += qv * kv.z;
                s[i][3] += qv * kv.w;
            }
        }

        bool diag = (kt == qt);
#pragma unroll
        for (int i = 0; i < 4; i++)
#pragma unroll
            for (int j = 0; j < 4; j++) {
                s[i][j] *= 0.125f;                         // 1/sqrt(64)
                if (diag && (tx * 4 + j > ty * 4 + i)) s[i][j] = -1e30f;
            }

        // online softmax (reduce over 16 threads sharing the row group)
        float mloc[4];
#pragma unroll
        for (int i = 0; i < 4; i++)
            mloc[i] = fmaxf(fmaxf(s[i][0], s[i][1]), fmaxf(s[i][2], s[i][3]));
#pragma unroll
        for (int off = 8; off >= 1; off >>= 1)
#pragma unroll
            for (int i = 0; i < 4; i++)
                mloc[i] = fmaxf(mloc[i], __shfl_xor_sync(0xffffffffu, mloc[i], off, 16));

        float mnew[4], scl[4];
#pragma unroll
        for (int i = 0; i < 4; i++) {
            mnew[i] = fmaxf(m[i], mloc[i]);
            scl[i]  = expf(m[i] - mnew[i]);
            m[i]    = mnew[i];
        }
#pragma unroll
        for (int i = 0; i < 4; i++)
#pragma unroll
            for (int j = 0; j < 4; j++)
                s[i][j] = expf(s[i][j] - mnew[i]);

        float lloc[4];
#pragma unroll
        for (int i = 0; i < 4; i++)
            lloc[i] = s[i][0] + s[i][1] + s[i][2] + s[i][3];
#pragma unroll
        for (int off = 8; off >= 1; off >>= 1)
#pragma unroll
            for (int i = 0; i < 4; i++)
                lloc[i] += __shfl_xor_sync(0xffffffffu, lloc[i], off, 16);
#pragma unroll
        for (int i = 0; i < 4; i++) {
            l[i] = l[i] * scl[i] + lloc[i];
#pragma unroll
            for (int j = 0; j < 4; j++) o[i][j] *= scl[i];
        }

        __syncthreads();   // all threads done reading Kt before overwrite
#pragma unroll
        for (int i = 0; i < 4; i++) {
            float4 p4;
            p4.x = s[i][0]; p4.y = s[i][1]; p4.z = s[i][2]; p4.w = s[i][3];
            *(float4*)&KP[(ty * 4 + i) * ATS + tx * 4] = p4;
        }
        __syncthreads();

        // O += P @ V  (thread owns rows ty*4.., dims tx*4..)
        for (int kk = 0; kk < 64; kk++) {
            float4 vv = *(float4*)&Vs[kk * ATS + tx * 4];
#pragma unroll
            for (int i = 0; i < 4; i++) {
                float pv = KP[(ty * 4 + i) * ATS + kk];
                o[i][0] += pv * vv.x;
                o[i][1] += pv * vv.y;
                o[i][2] += pv * vv.z;
                o[i][3] += pv * vv.w;
            }
        }
    }

    // write out: [b, s, h*HD + d]
#pragma unroll
    for (int i = 0; i < 4; i++) {
        float inv = 1.0f / l[i];
        int row = qt * 64 + ty * 4 + i;
        float4 r;
        r.x = o[i][0] * inv;
        r.y = o[i][1] * inv;
        r.z = o[i][2] * inv;
        r.w = o[i][3] * inv;
        *(float4*)&Out[((size_t)b * S_ + row) * HID_ + h * HD_ + tx * 4] = r;
    }
}

// ---------------- launch ----------------------------------------------------
extern "C" void kernel_launch(void* const* d_in, const int* in_sizes, int n_in,
                              void* d_out, int out_size) {
    const float* hidden  = (const float*)d_in[0];
    const float* w_qkv   = (const float*)d_in[1];
    const float* w_dense = (const float*)d_in[2];
    const float* b_dense = (const float*)d_in[3];
    float* out = (float*)d_out;

    void *p_qkv, *p_attno;
    cudaGetSymbolAddress(&p_qkv, g_qkv);
    cudaGetSymbolAddress(&p_attno, g_attno);

    // RoPE tables
    rope_table_kernel<<<(S_ * HD_ + 255) / 256, 256>>>();

    // fused QKV GEMM: [4096,1024] @ [1024,3072]
    {
        dim3 grid(QKV_N / 128, M_ / 128);
        gemm_kernel<<<grid, 256>>>(hidden, w_qkv, nullptr, (float*)p_qkv,
                                   M_, QKV_N, HID_);
    }

    // split + RoPE + relayout
    qkv_transform_kernel<<<(B_ * NH_ * S_ * HD_) / 256, 256>>>();

    // attention
    {
        size_t smem = 3 * 64 * ATS * sizeof(float);   // 52224 B
        cudaFuncSetAttribute(attn_kernel,
                             cudaFuncAttributeMaxDynamicSharedMemorySize,
                             (int)smem);
        dim3 grid(S_ / 64, B_ * NH_);
        attn_kernel<<<grid, 256, smem>>>((float*)p_attno);
    }

    // dense projection + bias: [4096,1024] @ [1024,1024] + b
    {
        dim3 grid(HID_ / 128, M_ / 128);
        gemm_kernel<<<grid, 256>>>((const float*)p_attno, w_dense, b_dense, out,
                                   M_, HID_, HID_);
    }
}

// round 2
// speedup vs baseline: 2.5776x; 2.5776x over previous
#include <cuda_runtime.h>
#include <cuda_bf16.h>
#include <math.h>

#define B_   2
#define S_   2048
#define HID_ 1024
#define NH_  16
#define HD_  64
#define M_   (B_ * S_)        // 4096
#define QKV_N (3 * HID_)      // 3072

// ---------------- scratch (device globals) ---------------------------------
__device__ float g_qkv[M_ * QKV_N];
__device__ float g_q[B_ * NH_ * S_ * HD_];     // [b,h,s,d]
__device__ float g_k[B_ * NH_ * S_ * HD_];
__device__ float g_v[B_ * NH_ * S_ * HD_];
__device__ float g_attno[M_ * HID_];
__device__ float g_cos[S_ * HD_];
__device__ float g_sin[S_ * HD_];

// ---------------- helpers ---------------------------------------------------
__device__ __forceinline__ unsigned f2tf(float x) {
    unsigned r;
    asm("cvt.rna.tf32.f32 %0, %1;" : "=r"(r) : "f"(x));
    return r;
}
__device__ __forceinline__ void mma_tf32(float* c, const unsigned* a,
                                         unsigned b0, unsigned b1) {
    asm volatile(
        "mma.sync.aligned.m16n8k8.row.col.f32.tf32.tf32.f32 "
        "{%0,%1,%2,%3}, {%4,%5,%6,%7}, {%8,%9}, {%0,%1,%2,%3};\n"
        : "+f"(c[0]), "+f"(c[1]), "+f"(c[2]), "+f"(c[3])
        : "r"(a[0]), "r"(a[1]), "r"(a[2]), "r"(a[3]), "r"(b0), "r"(b1));
}
__device__ __forceinline__ void cp_async16(void* smem, const void* gmem) {
    unsigned s = (unsigned)__cvta_generic_to_shared(smem);
    asm volatile("cp.async.cg.shared.global [%0], [%1], 16;" :: "r"(s), "l"(gmem));
}
#define CP_COMMIT asm volatile("cp.async.commit_group;")
#define CP_WAIT0  asm volatile("cp.async.wait_group 0;")
#define CP_WAIT1  asm volatile("cp.async.wait_group 1;")

// ---------------- RoPE tables (double precision trig -> f32) ---------------
__global__ void rope_table_kernel() {
    int idx = blockIdx.x * blockDim.x + threadIdx.x;
    if (idx >= S_ * HD_) return;
    int s = idx >> 6;
    int d = idx & 63;
    int i = d & 31;
    double inv = pow(10000.0, -((double)(2 * i)) / (double)HD_);
    float freq = (float)s * (float)inv;
    g_cos[idx] = (float)cos((double)freq);
    g_sin[idx] = (float)sin((double)freq);
}

// ---------------- tf32 tensor-core GEMM: C = A[M,K] @ W[K,N] (+bias) -------
// 128x128x32 tile, 256 threads (8 warps as 4x2), warp tile 32x64.
#define ASTR 36
#define BSTR 136
#define ASZ  (128 * ASTR)
#define BSZ  (32 * BSTR)

__global__ __launch_bounds__(256)
void gemm_tc(const float* __restrict__ A, const float* __restrict__ W,
             const float* __restrict__ bias, float* __restrict__ C,
             int M, int N, int K) {
    extern __shared__ float sm[];
    float* As = sm;               // [2][128][36]
    float* Bs = sm + 2 * ASZ;     // [2][32][136]

    int tid  = threadIdx.x;
    int lane = tid & 31;
    int warp = tid >> 5;
    int row0 = blockIdx.y * 128;
    int col0 = blockIdx.x * 128;
    int wm = (warp & 3) * 32;
    int wn = (warp >> 2) * 64;

    float acc[2][8][4];
#pragma unroll
    for (int mt = 0; mt < 2; mt++)
#pragma unroll
        for (int nt = 0; nt < 8; nt++)
#pragma unroll
            for (int j = 0; j < 4; j++) acc[mt][nt][j] = 0.0f;

    auto load_tiles = [&](int st, int t) {
        int k0 = t * 32;
#pragma unroll
        for (int i = 0; i < 4; i++) {
            int id = tid + i * 256;
            int r = id >> 3, c4 = (id & 7) * 4;
            cp_async16(&As[st * ASZ + r * ASTR + c4],
                       &A[(size_t)(row0 + r) * K + k0 + c4]);
        }
#pragma unroll
        for (int i = 0; i < 4; i++) {
            int id = tid + i * 256;
            int r = id >> 5, n4 = (id & 31) * 4;
            cp_async16(&Bs[st * BSZ + r * BSTR + n4],
                       &W[(size_t)(k0 + r) * N + col0 + n4]);
        }
    };

    int nk = K / 32;
    load_tiles(0, 0);
    CP_COMMIT;

    for (int t = 0; t < nk; t++) {
        int st = t & 1;
        if (t + 1 < nk) { load_tiles(st ^ 1, t + 1); CP_COMMIT; CP_WAIT1; }
        else           { CP_WAIT0; }
        __syncthreads();

        const float* Ast = As + st * ASZ;
        const float* Bst = Bs + st * BSZ;
#pragma unroll
        for (int ks = 0; ks < 4; ks++) {
            int k0 = ks * 8;
            unsigned a[2][4];
#pragma unroll
            for (int mt = 0; mt < 2; mt++) {
                int m = wm + mt * 16 + (lane >> 2);
                int k = k0 + (lane & 3);
                a[mt][0] = f2tf(Ast[m * ASTR + k]);
                a[mt][1] = f2tf(Ast[(m + 8) * ASTR + k]);
                a[mt][2] = f2tf(Ast[m * ASTR + k + 4]);
                a[mt][3] = f2tf(Ast[(m + 8) * ASTR + k + 4]);
            }
            unsigned b[8][2];
#pragma unroll
            for (int nt = 0; nt < 8; nt++) {
                int n = wn + nt * 8 + (lane >> 2);
                int k = k0 + (lane & 3);
                b[nt][0] = f2tf(Bst[k * BSTR + n]);
                b[nt][1] = f2tf(Bst[(k + 4) * BSTR + n]);
            }
#pragma unroll
            for (int mt = 0; mt < 2; mt++)
#pragma unroll
                for (int nt = 0; nt < 8; nt++)
                    mma_tf32(acc[mt][nt], a[mt], b[nt][0], b[nt][1]);
        }
        __syncthreads();
    }

    // epilogue
#pragma unroll
    for (int mt = 0; mt < 2; mt++) {
        int r = row0 + wm + mt * 16 + (lane >> 2);
#pragma unroll
        for (int nt = 0; nt < 8; nt++) {
            int c = col0 + wn + nt * 8 + 2 * (lane & 3);
            float bx = 0.f, by = 0.f;
            if (bias) { bx = bias[c]; by = bias[c + 1]; }
            float2 lo, hi;
            lo.x = acc[mt][nt][0] + bx; lo.y = acc[mt][nt][1] + by;
            hi.x = acc[mt][nt][2] + bx; hi.y = acc[mt][nt][3] + by;
            *(float2*)&C[(size_t)r * N + c]       = lo;
            *(float2*)&C[(size_t)(r + 8) * N + c] = hi;
        }
    }
}

// ---------------- qkv -> q,k,v with RoPE, layout [b,h,s,d] ------------------
__global__ void qkv_transform_kernel() {
    int e = blockIdx.x * blockDim.x + threadIdx.x;
    if (e >= B_ * NH_ * S_ * HD_) return;
    int d = e & 63;
    int s = (e >> 6) & (S_ - 1);
    int h = (e >> 17) & (NH_ - 1);
    int b = e >> 21;

    size_t base = ((size_t)(b * S_ + s)) * QKV_N;
    int c  = h * HD_ + d;
    int dp = (d < 32) ? d + 32 : d - 32;
    int c2 = h * HD_ + dp;
    float sgn = (d < 32) ? -1.0f : 1.0f;

    float qr = g_qkv[base + c];
    float q2 = g_qkv[base + c2];
    float kr = g_qkv[base + HID_ + c];
    float k2 = g_qkv[base + HID_ + c2];
    float vr = g_qkv[base + 2 * HID_ + c];

    float cs = g_cos[s * HD_ + d];
    float sn = g_sin[s * HD_ + d];

    g_q[e] = qr * cs + sgn * q2 * sn;
    g_k[e] = kr * cs + sgn * k2 * sn;
    g_v[e] = vr;
}

// ---------------- causal flash attention (tf32 mma) --------------------------
// grid: (S/128, B*NH), 256 threads (8 warps, each 16 q-rows).
#define KSTR 68
#define VSTR 72
#define KSZ  (64 * KSTR)
#define VSZ  (64 * VSTR)

__global__ __launch_bounds__(256)
void attn_tc(float* __restrict__ Out) {
    extern __shared__ float sm[];
    float* Ks = sm;               // [2][64][68]
    float* Vs = sm + 2 * KSZ;     // [2][64][72]

    int qblk = blockIdx.x;
    int bh   = blockIdx.y;
    int qb   = qblk * 128;
    int qt2  = qblk * 2;
    int b = bh >> 4, h = bh & 15;

    const float* Qb = g_q + (size_t)bh * S_ * HD_;
    const float* Kb = g_k + (size_t)bh * S_ * HD_;
    const float* Vb = g_v + (size_t)bh * S_ * HD_;

    int tid  = threadIdx.x;
    int lane = tid & 31;
    int warp = tid >> 5;
    int row_lo = qb + warp * 16 + (lane >> 2);

    // Q fragments (scaled by 1/sqrt(HD)) held in regs for whole loop
    unsigned qf[8][4];
#pragma unroll
    for (int ks = 0; ks < 8; ks++) {
        int d = ks * 8 + (lane & 3);
        qf[ks][0] = f2tf(Qb[(size_t)row_lo * 64 + d] * 0.125f);
        qf[ks][1] = f2tf(Qb[(size_t)(row_lo + 8) * 64 + d] * 0.125f);
        qf[ks][2] = f2tf(Qb[(size_t)row_lo * 64 + d + 4] * 0.125f);
        qf[ks][3] = f2tf(Qb[(size_t)(row_lo + 8) * 64 + d + 4] * 0.125f);
    }

    float o[8][4];
#pragma unroll
    for (int nt = 0; nt < 8; nt++)
#pragma unroll
        for (int j = 0; j < 4; j++) o[nt][j] = 0.0f;
    float m_lo = -1e30f, m_hi = -1e30f, l_lo = 0.0f, l_hi = 0.0f;

    auto load_kv = [&](int st, int kt) {
#pragma unroll
        for (int i = 0; i < 4; i++) {
            int id = tid + i * 256;
            int r = id >> 4, d4 = (id & 15) * 4;
            cp_async16(&Ks[st * KSZ + r * KSTR + d4],
                       &Kb[(size_t)(kt * 64 + r) * 64 + d4]);
            cp_async16(&Vs[st * VSZ + r * VSTR + d4],
                       &Vb[(size_t)(kt * 64 + r) * 64 + d4]);
        }
    };

    int nkt = qt2 + 2;
    load_kv(0, 0);
    CP_COMMIT;

    for (int kt = 0; kt < nkt; kt++) {
        int st = kt & 1;
        if (kt + 1 < nkt) { load_kv(st ^ 1, kt + 1); CP_COMMIT; CP_WAIT1; }
        else              { CP_WAIT0; }
        __syncthreads();

        if (kt * 64 <= qb + warp * 16 + 15) {   // warp has live rows
            const float* Kst = Ks + st * KSZ;
            const float* Vst = Vs + st * VSZ;

            // S = Q @ K^T
            float s[8][4];
#pragma unroll
            for (int nt = 0; nt < 8; nt++)
#pragma unroll
                for (int j = 0; j < 4; j++) s[nt][j] = 0.0f;

#pragma unroll
            for (int ks = 0; ks < 8; ks++) {
                int kd = ks * 8 + (lane & 3);
#pragma unroll
                for (int nt = 0; nt < 8; nt++) {
                    int tok = nt * 8 + (lane >> 2);
                    unsigned b0 = f2tf(Kst[tok * KSTR + kd]);
                    unsigned b1 = f2tf(Kst[tok * KSTR + kd + 4]);
                    mma_tf32(s[nt], qf[ks], b0, b1);
                }
            }

            // causal mask
            if (kt >= qt2) {
#pragma unroll
                for (int nt = 0; nt < 8; nt++) {
                    int key0 = kt * 64 + nt * 8 + 2 * (lane & 3);
                    if (key0     > row_lo)     s[nt][0] = -1e30f;
                    if (key0 + 1 > row_lo)     s[nt][1] = -1e30f;
                    if (key0     > row_lo + 8) s[nt][2] = -1e30f;
                    if (key0 + 1 > row_lo + 8) s[nt][3] = -1e30f;
                }
            }

            // online softmax
            float mloc_lo = -1e30f, mloc_hi = -1e30f;
#pragma unroll
            for (int nt = 0; nt < 8; nt++) {
                mloc_lo = fmaxf(mloc_lo, fmaxf(s[nt][0], s[nt][1]));
                mloc_hi = fmaxf(mloc_hi, fmaxf(s[nt][2], s[nt][3]));
            }
            mloc_lo = fmaxf(mloc_lo, __shfl_xor_sync(0xffffffffu, mloc_lo, 1));
            mloc_lo = fmaxf(mloc_lo, __shfl_xor_sync(0xffffffffu, mloc_lo, 2));
            mloc_hi = fmaxf(mloc_hi, __shfl_xor_sync(0xffffffffu, mloc_hi, 1));
            mloc_hi = fmaxf(mloc_hi, __shfl_xor_sync(0xffffffffu, mloc_hi, 2));

            float mn_lo = fmaxf(m_lo, mloc_lo);
            float mn_hi = fmaxf(m_hi, mloc_hi);
            float scl_lo = __expf(m_lo - mn_lo);
            float scl_hi = __expf(m_hi - mn_hi);
            m_lo = mn_lo; m_hi = mn_hi;

            float lloc_lo = 0.0f, lloc_hi = 0.0f;
#pragma unroll
            for (int nt = 0; nt < 8; nt++) {
                s[nt][0] = __expf(s[nt][0] - m_lo);
                s[nt][1] = __expf(s[nt][1] - m_lo);
                s[nt][2] = __expf(s[nt][2] - m_hi);
                s[nt][3] = __expf(s[nt][3] - m_hi);
                lloc_lo += s[nt][0] + s[nt][1];
                lloc_hi += s[nt][2] + s[nt][3];
            }
            lloc_lo += __shfl_xor_sync(0xffffffffu, lloc_lo, 1);
            lloc_lo += __shfl_xor_sync(0xffffffffu, lloc_lo, 2);
            lloc_hi += __shfl_xor_sync(0xffffffffu, lloc_hi, 1);
            lloc_hi += __shfl_xor_sync(0xffffffffu, lloc_hi, 2);
            l_lo = l_lo * scl_lo + lloc_lo;
            l_hi = l_hi * scl_hi + lloc_hi;

#pragma unroll
            for (int nt = 0; nt < 8; nt++) {
                o[nt][0] *= scl_lo; o[nt][1] *= scl_lo;
                o[nt][2] *= scl_hi; o[nt][3] *= scl_hi;
            }

            // P (C-layout) -> A fragments via shuffles, then O += P @ V
            int lane_lo = (lane & ~3) | ((lane & 3) >> 1);
            int lane_hi = lane_lo + 2;
            int sel = lane & 1;
#pragma unroll
            for (int kt2 = 0; kt2 < 8; kt2++) {
                float v0, v1;
                v0 = __shfl_sync(0xffffffffu, s[kt2][0], lane_lo);
                v1 = __shfl_sync(0xffffffffu, s[kt2][1], lane_lo);
                float p0 = sel ? v1 : v0;
                v0 = __shfl_sync(0xffffffffu, s[kt2][2], lane_lo);
                v1 = __shfl_sync(0xffffffffu, s[kt2][3], lane_lo);
                float p1 = sel ? v1 : v0;
                v0 = __shfl_sync(0xffffffffu, s[kt2][0], lane_hi);
                v1 = __shfl_sync(0xffffffffu, s[kt2][1], lane_hi);
                float p2 = sel ? v1 : v0;
                v0 = __shfl_sync(0xffffffffu, s[kt2][2], lane_hi);
                v1 = __shfl_sync(0xffffffffu, s[kt2][3], lane_hi);
                float p3 = sel ? v1 : v0;

                unsigned a[4];
                a[0] = f2tf(p0); a[1] = f2tf(p1);
                a[2] = f2tf(p2); a[3] = f2tf(p3);

                int tok = kt2 * 8 + (lane & 3);
#pragma unroll
                for (int nt = 0; nt < 8; nt++) {
                    int d = nt * 8 + (lane >> 2);
                    unsigned b0 = f2tf(Vst[tok * VSTR + d]);
                    unsigned b1 = f2tf(Vst[(tok + 4) * VSTR + d]);
                    mma_tf32(o[nt], a, b0, b1);
                }
            }
        }
        __syncthreads();
    }

    // write out: [b, s, h*64 + d]
    float inv_lo = 1.0f / l_lo;
    float inv_hi = 1.0f / l_hi;
#pragma unroll
    for (int nt = 0; nt < 8; nt++) {
        int col = h * 64 + nt * 8 + 2 * (lane & 3);
        float2 lo, hi;
        lo.x = o[nt][0] * inv_lo; lo.y = o[nt][1] * inv_lo;
        hi.x = o[nt][2] * inv_hi; hi.y = o[nt][3] * inv_hi;
        *(float2*)&Out[((size_t)b * S_ + row_lo) * HID_ + col]       = lo;
        *(float2*)&Out[((size_t)b * S_ + row_lo + 8) * HID_ + col]   = hi;
    }
}

// ---------------- launch ----------------------------------------------------
extern "C" void kernel_launch(void* const* d_in, const int* in_sizes, int n_in,
                              void* d_out, int out_size) {
    const float* hidden  = (const float*)d_in[0];
    const float* w_qkv   = (const float*)d_in[1];
    const float* w_dense = (const float*)d_in[2];
    const float* b_dense = (const float*)d_in[3];
    float* out = (float*)d_out;

    void *p_qkv, *p_attno;
    cudaGetSymbolAddress(&p_qkv, g_qkv);
    cudaGetSymbolAddress(&p_attno, g_attno);

    rope_table_kernel<<<(S_ * HD_ + 255) / 256, 256>>>();

    size_t gemm_smem = (size_t)(2 * ASZ + 2 * BSZ) * sizeof(float);   // 71680
    cudaFuncSetAttribute(gemm_tc, cudaFuncAttributeMaxDynamicSharedMemorySize,
                         (int)gemm_smem);

    {
        dim3 grid(QKV_N / 128, M_ / 128);
        gemm_tc<<<grid, 256, gemm_smem>>>(hidden, w_qkv, nullptr, (float*)p_qkv,
                                          M_, QKV_N, HID_);
    }

    qkv_transform_kernel<<<(B_ * NH_ * S_ * HD_) / 256, 256>>>();

    {
        size_t smem = (size_t)(2 * KSZ + 2 * VSZ) * sizeof(float);    // 71680
        cudaFuncSetAttribute(attn_tc, cudaFuncAttributeMaxDynamicSharedMemorySize,
                             (int)smem);
        dim3 grid(S_ / 128, B_ * NH_);
        attn_tc<<<grid, 256, smem>>>((float*)p_attno);
    }

    {
        dim3 grid(HID_ / 128, M_ / 128);
        gemm_tc<<<grid, 256, gemm_smem>>>((const float*)p_attno, w_dense, b_dense,
                                          out, M_, HID_, HID_);
    }
}

// round 3
// speedup vs baseline: 2.9830x; 1.1573x over previous
#include <cuda_runtime.h>
#include <cuda_bf16.h>
#include <math.h>

#define B_   2
#define S_   2048
#define HID_ 1024
#define NH_  16
#define HD_  64
#define M_   (B_ * S_)        // 4096
#define QKV_N (3 * HID_)      // 3072

// ---------------- scratch (device globals) ---------------------------------
__device__ float g_qkv[M_ * QKV_N];
__device__ float g_q[B_ * NH_ * S_ * HD_];     // [b,h,s,d] tf32-rounded, pre-scaled
__device__ float g_k[B_ * NH_ * S_ * HD_];     // tf32-rounded
__device__ float g_v[B_ * NH_ * S_ * HD_];     // tf32-rounded
__device__ float g_attno[M_ * HID_];           // tf32-rounded
__device__ float g_cos[S_ * HD_];
__device__ float g_sin[S_ * HD_];
__device__ float g_hid_r[M_ * HID_];           // tf32-rounded hidden
__device__ float g_wqkv_r[HID_ * QKV_N];       // tf32-rounded w_qkv
__device__ float g_wdense_r[HID_ * HID_];      // tf32-rounded w_dense

// ---------------- helpers ---------------------------------------------------
__device__ __forceinline__ unsigned f2tf(float x) {
    unsigned r;
    asm("cvt.rna.tf32.f32 %0, %1;" : "=r"(r) : "f"(x));
    return r;
}
__device__ __forceinline__ float rtf(float x) {   // tf32-rounded value as float
    return __uint_as_float(f2tf(x));
}
__device__ __forceinline__ void mma_tf32(float* c, const unsigned* a,
                                         unsigned b0, unsigned b1) {
    asm volatile(
        "mma.sync.aligned.m16n8k8.row.col.f32.tf32.tf32.f32 "
        "{%0,%1,%2,%3}, {%4,%5,%6,%7}, {%8,%9}, {%0,%1,%2,%3};\n"
        : "+f"(c[0]), "+f"(c[1]), "+f"(c[2]), "+f"(c[3])
        : "r"(a[0]), "r"(a[1]), "r"(a[2]), "r"(a[3]), "r"(b0), "r"(b1));
}
__device__ __forceinline__ void cp_async16(void* smem, const void* gmem) {
    unsigned s = (unsigned)__cvta_generic_to_shared(smem);
    asm volatile("cp.async.cg.shared.global [%0], [%1], 16;" :: "r"(s), "l"(gmem));
}
#define CP_COMMIT asm volatile("cp.async.commit_group;")
#define CP_WAIT0  asm volatile("cp.async.wait_group 0;")
#define CP_WAIT1  asm volatile("cp.async.wait_group 1;")

// ---------------- prep: round a buffer to tf32 ------------------------------
__global__ void round_tf32_kernel(const float* __restrict__ in,
                                  float* __restrict__ out, int n4) {
    int i = blockIdx.x * blockDim.x + threadIdx.x;
    if (i >= n4) return;
    float4 f = ((const float4*)in)[i];
    f.x = rtf(f.x); f.y = rtf(f.y); f.z = rtf(f.z); f.w = rtf(f.w);
    ((float4*)out)[i] = f;
}

// ---------------- RoPE tables (double precision trig -> f32) ---------------
__global__ void rope_table_kernel() {
    int idx = blockIdx.x * blockDim.x + threadIdx.x;
    if (idx >= S_ * HD_) return;
    int s = idx >> 6;
    int d = idx & 63;
    int i = d & 31;
    double inv = pow(10000.0, -((double)(2 * i)) / (double)HD_);
    float freq = (float)s * (float)inv;
    g_cos[idx] = (float)cos((double)freq);
    g_sin[idx] = (float)sin((double)freq);
}

// ---------------- tf32 tensor-core GEMM: C = A[M,K] @ W[K,N] (+bias) -------
// A and W must already be tf32-rounded. 128x128x32 tile, 256 threads.
#define ASTR 36
#define BSTR 136
#define ASZ  (128 * ASTR)
#define BSZ  (32 * BSTR)

__global__ __launch_bounds__(256, 2)
void gemm_tc(const float* __restrict__ A, const float* __restrict__ W,
             const float* __restrict__ bias, float* __restrict__ C,
             int M, int N, int K, int round_out) {
    extern __shared__ float sm[];
    float* As = sm;               // [2][128][36]
    float* Bs = sm + 2 * ASZ;     // [2][32][136]

    int tid  = threadIdx.x;
    int lane = tid & 31;
    int warp = tid >> 5;
    int row0 = blockIdx.y * 128;
    int col0 = blockIdx.x * 128;
    int wm = (warp & 3) * 32;
    int wn = (warp >> 2) * 64;

    float acc[2][8][4];
#pragma unroll
    for (int mt = 0; mt < 2; mt++)
#pragma unroll
        for (int nt = 0; nt < 8; nt++)
#pragma unroll
            for (int j = 0; j < 4; j++) acc[mt][nt][j] = 0.0f;

    auto load_tiles = [&](int st, int t) {
        int k0 = t * 32;
#pragma unroll
        for (int i = 0; i < 4; i++) {
            int id = tid + i * 256;
            int r = id >> 3, c4 = (id & 7) * 4;
            cp_async16(&As[st * ASZ + r * ASTR + c4],
                       &A[(size_t)(row0 + r) * K + k0 + c4]);
        }
#pragma unroll
        for (int i = 0; i < 4; i++) {
            int id = tid + i * 256;
            int r = id >> 5, n4 = (id & 31) * 4;
            cp_async16(&Bs[st * BSZ + r * BSTR + n4],
                       &W[(size_t)(k0 + r) * N + col0 + n4]);
        }
    };

    int nk = K / 32;
    load_tiles(0, 0);
    CP_COMMIT;

    for (int t = 0; t < nk; t++) {
        int st = t & 1;
        if (t + 1 < nk) { load_tiles(st ^ 1, t + 1); CP_COMMIT; CP_WAIT1; }
        else           { CP_WAIT0; }
        __syncthreads();

        const unsigned* Ast = (const unsigned*)(As + st * ASZ);
        const unsigned* Bst = (const unsigned*)(Bs + st * BSZ);
#pragma unroll
        for (int ks = 0; ks < 4; ks++) {
            int k0 = ks * 8;
            unsigned a[2][4];
#pragma unroll
            for (int mt = 0; mt < 2; mt++) {
                int m = wm + mt * 16 + (lane >> 2);
                int k = k0 + (lane & 3);
                a[mt][0] = Ast[m * ASTR + k];
                a[mt][1] = Ast[(m + 8) * ASTR + k];
                a[mt][2] = Ast[m * ASTR + k + 4];
                a[mt][3] = Ast[(m + 8) * ASTR + k + 4];
            }
            unsigned b[8][2];
#pragma unroll
            for (int nt = 0; nt < 8; nt++) {
                int n = wn + nt * 8 + (lane >> 2);
                int k = k0 + (lane & 3);
                b[nt][0] = Bst[k * BSTR + n];
                b[nt][1] = Bst[(k + 4) * BSTR + n];
            }
#pragma unroll
            for (int mt = 0; mt < 2; mt++)
#pragma unroll
                for (int nt = 0; nt < 8; nt++)
                    mma_tf32(acc[mt][nt], a[mt], b[nt][0], b[nt][1]);
        }
        __syncthreads();
    }

    // epilogue
#pragma unroll
    for (int mt = 0; mt < 2; mt++) {
        int r = row0 + wm + mt * 16 + (lane >> 2);
#pragma unroll
        for (int nt = 0; nt < 8; nt++) {
            int c = col0 + wn + nt * 8 + 2 * (lane & 3);
            float bx = 0.f, by = 0.f;
            if (bias) { bx = bias[c]; by = bias[c + 1]; }
            float2 lo, hi;
            lo.x = acc[mt][nt][0] + bx; lo.y = acc[mt][nt][1] + by;
            hi.x = acc[mt][nt][2] + bx; hi.y = acc[mt][nt][3] + by;
            if (round_out) {
                lo.x = rtf(lo.x); lo.y = rtf(lo.y);
                hi.x = rtf(hi.x); hi.y = rtf(hi.y);
            }
            *(float2*)&C[(size_t)r * N + c]       = lo;
            *(float2*)&C[(size_t)(r + 8) * N + c] = hi;
        }
    }
}

// ---------------- qkv -> q,k,v with RoPE, tf32-rounded, layout [b,h,s,d] ----
__global__ void qkv_transform_kernel() {
    int e = blockIdx.x * blockDim.x + threadIdx.x;
    if (e >= B_ * NH_ * S_ * HD_) return;
    int d = e & 63;
    int s = (e >> 6) & (S_ - 1);
    int h = (e >> 17) & (NH_ - 1);
    int b = e >> 21;

    size_t base = ((size_t)(b * S_ + s)) * QKV_N;
    int c  = h * HD_ + d;
    int dp = (d < 32) ? d + 32 : d - 32;
    int c2 = h * HD_ + dp;
    float sgn = (d < 32) ? -1.0f : 1.0f;

    float qr = g_qkv[base + c];
    float q2 = g_qkv[base + c2];
    float kr = g_qkv[base + HID_ + c];
    float k2 = g_qkv[base + HID_ + c2];
    float vr = g_qkv[base + 2 * HID_ + c];

    float cs = g_cos[s * HD_ + d];
    float sn = g_sin[s * HD_ + d];

    g_q[e] = rtf((qr * cs + sgn * q2 * sn) * 0.125f);   // pre-scaled 1/sqrt(64)
    g_k[e] = rtf(kr * cs + sgn * k2 * sn);
    g_v[e] = rtf(vr);
}

// ---------------- causal flash attention (tf32 mma) --------------------------
#define KSTR 68
#define VSTR 72
#define KSZ  (64 * KSTR)
#define VSZ  (64 * VSTR)

__global__ __launch_bounds__(256, 2)
void attn_tc(float* __restrict__ Out) {
    extern __shared__ float sm[];
    float* Ks = sm;               // [2][64][68]
    float* Vs = sm + 2 * KSZ;     // [2][64][72]

    int qblk = gridDim.x - 1 - blockIdx.x;   // big blocks launch first
    int bh   = blockIdx.y;
    int qb   = qblk * 128;
    int qt2  = qblk * 2;
    int b = bh >> 4, h = bh & 15;

    const float* Qb = g_q + (size_t)bh * S_ * HD_;
    const float* Kb = g_k + (size_t)bh * S_ * HD_;
    const float* Vb = g_v + (size_t)bh * S_ * HD_;

    int tid  = threadIdx.x;
    int lane = tid & 31;
    int warp = tid >> 5;
    int row_lo = qb + warp * 16 + (lane >> 2);

    // Q fragments (already tf32-rounded + scaled) held in regs for whole loop
    unsigned qf[8][4];
#pragma unroll
    for (int ks = 0; ks < 8; ks++) {
        int d = ks * 8 + (lane & 3);
        qf[ks][0] = __float_as_uint(Qb[(size_t)row_lo * 64 + d]);
        qf[ks][1] = __float_as_uint(Qb[(size_t)(row_lo + 8) * 64 + d]);
        qf[ks][2] = __float_as_uint(Qb[(size_t)row_lo * 64 + d + 4]);
        qf[ks][3] = __float_as_uint(Qb[(size_t)(row_lo + 8) * 64 + d + 4]);
    }

    float o[8][4];
#pragma unroll
    for (int nt = 0; nt < 8; nt++)
#pragma unroll
        for (int j = 0; j < 4; j++) o[nt][j] = 0.0f;
    float m_lo = -1e30f, m_hi = -1e30f, l_lo = 0.0f, l_hi = 0.0f;

    auto load_kv = [&](int st, int kt) {
#pragma unroll
        for (int i = 0; i < 4; i++) {
            int id = tid + i * 256;
            int r = id >> 4, d4 = (id & 15) * 4;
            cp_async16(&Ks[st * KSZ + r * KSTR + d4],
                       &Kb[(size_t)(kt * 64 + r) * 64 + d4]);
            cp_async16(&Vs[st * VSZ + r * VSTR + d4],
                       &Vb[(size_t)(kt * 64 + r) * 64 + d4]);
        }
    };

    int nkt = qt2 + 2;
    load_kv(0, 0);
    CP_COMMIT;

    for (int kt = 0; kt < nkt; kt++) {
        int st = kt & 1;
        if (kt + 1 < nkt) { load_kv(st ^ 1, kt + 1); CP_COMMIT; CP_WAIT1; }
        else              { CP_WAIT0; }
        __syncthreads();

        if (kt * 64 <= qb + warp * 16 + 15) {
            const unsigned* Kst = (const unsigned*)(Ks + st * KSZ);
            const unsigned* Vst = (const unsigned*)(Vs + st * VSZ);

            // S = Q @ K^T
            float s[8][4];
#pragma unroll
            for (int nt = 0; nt < 8; nt++)
#pragma unroll
                for (int j = 0; j < 4; j++) s[nt][j] = 0.0f;

#pragma unroll
            for (int ks = 0; ks < 8; ks++) {
                int kd = ks * 8 + (lane & 3);
#pragma unroll
                for (int nt = 0; nt < 8; nt++) {
                    int tok = nt * 8 + (lane >> 2);
                    unsigned b0 = Kst[tok * KSTR + kd];
                    unsigned b1 = Kst[tok * KSTR + kd + 4];
                    mma_tf32(s[nt], qf[ks], b0, b1);
                }
            }

            // causal mask
            if (kt >= qt2) {
#pragma unroll
                for (int nt = 0; nt < 8; nt++) {
                    int key0 = kt * 64 + nt * 8 + 2 * (lane & 3);
                    if (key0     > row_lo)     s[nt][0] = -1e30f;
                    if (key0 + 1 > row_lo)     s[nt][1] = -1e30f;
                    if (key0     > row_lo + 8) s[nt][2] = -1e30f;
                    if (key0 + 1 > row_lo + 8) s[nt][3] = -1e30f;
                }
            }

            // online softmax
            float mloc_lo = -1e30f, mloc_hi = -1e30f;
#pragma unroll
            for (int nt = 0; nt < 8; nt++) {
                mloc_lo = fmaxf(mloc_lo, fmaxf(s[nt][0], s[nt][1]));
                mloc_hi = fmaxf(mloc_hi, fmaxf(s[nt][2], s[nt][3]));
            }
            mloc_lo = fmaxf(mloc_lo, __shfl_xor_sync(0xffffffffu, mloc_lo, 1));
            mloc_lo = fmaxf(mloc_lo, __shfl_xor_sync(0xffffffffu, mloc_lo, 2));
            mloc_hi = fmaxf(mloc_hi, __shfl_xor_sync(0xffffffffu, mloc_hi, 1));
            mloc_hi = fmaxf(mloc_hi, __shfl_xor_sync(0xffffffffu, mloc_hi, 2));

            float mn_lo = fmaxf(m_lo, mloc_lo);
            float mn_hi = fmaxf(m_hi, mloc_hi);
            float scl_lo = __expf(m_lo - mn_lo);
            float scl_hi = __expf(m_hi - mn_hi);
            m_lo = mn_lo; m_hi = mn_hi;

            float lloc_lo = 0.0f, lloc_hi = 0.0f;
#pragma unroll
            for (int nt = 0; nt < 8; nt++) {
                s[nt][0] = __expf(s[nt][0] - m_lo);
                s[nt][1] = __expf(s[nt][1] - m_lo);
                s[nt][2] = __expf(s[nt][2] - m_hi);
                s[nt][3] = __expf(s[nt][3] - m_hi);
                lloc_lo += s[nt][0] + s[nt][1];
                lloc_hi += s[nt][2] + s[nt][3];
            }
            lloc_lo += __shfl_xor_sync(0xffffffffu, lloc_lo, 1);
            lloc_lo += __shfl_xor_sync(0xffffffffu, lloc_lo, 2);
            lloc_hi += __shfl_xor_sync(0xffffffffu, lloc_hi, 1);
            lloc_hi += __shfl_xor_sync(0xffffffffu, lloc_hi, 2);
            l_lo = l_lo * scl_lo + lloc_lo;
            l_hi = l_hi * scl_hi + lloc_hi;

#pragma unroll
            for (int nt = 0; nt < 8; nt++) {
                o[nt][0] *= scl_lo; o[nt][1] *= scl_lo;
                o[nt][2] *= scl_hi; o[nt][3] *= scl_hi;
            }

            // P (C-layout) -> A fragments via shuffles, then O += P @ V
            int lane_lo = (lane & ~3) | ((lane & 3) >> 1);
            int lane_hi = lane_lo + 2;
            int sel = lane & 1;
#pragma unroll
            for (int kt2 = 0; kt2 < 8; kt2++) {
                float v0, v1;
                v0 = __shfl_sync(0xffffffffu, s[kt2][0], lane_lo);
                v1 = __shfl_sync(0xffffffffu, s[kt2][1], lane_lo);
                float p0 = sel ? v1 : v0;
                v0 = __shfl_sync(0xffffffffu, s[kt2][2], lane_lo);
                v1 = __shfl_sync(0xffffffffu, s[kt2][3], lane_lo);
                float p1 = sel ? v1 : v0;
                v0 = __shfl_sync(0xffffffffu, s[kt2][0], lane_hi);
                v1 = __shfl_sync(0xffffffffu, s[kt2][1], lane_hi);
                float p2 = sel ? v1 : v0;
                v0 = __shfl_sync(0xffffffffu, s[kt2][2], lane_hi);
                v1 = __shfl_sync(0xffffffffu, s[kt2][3], lane_hi);
                float p3 = sel ? v1 : v0;

                unsigned a[4];
                a[0] = f2tf(p0); a[1] = f2tf(p1);
                a[2] = f2tf(p2); a[3] = f2tf(p3);

                int tok = kt2 * 8 + (lane & 3);
#pragma unroll
                for (int nt = 0; nt < 8; nt++) {
                    int d = nt * 8 + (lane >> 2);
                    unsigned b0 = Vst[tok * VSTR + d];
                    unsigned b1 = Vst[(tok + 4) * VSTR + d];
                    mma_tf32(o[nt], a, b0, b1);
                }
            }
        }
        __syncthreads();
    }

    // write out tf32-rounded (feeds tf32 dense GEMM): [b, s, h*64 + d]
    float inv_lo = 1.0f / l_lo;
    float inv_hi = 1.0f / l_hi;
#pragma unroll
    for (int nt = 0; nt < 8; nt++) {
        int col = h * 64 + nt * 8 + 2 * (lane & 3);
        float2 lo, hi;
        lo.x = rtf(o[nt][0] * inv_lo); lo.y = rtf(o[nt][1] * inv_lo);
        hi.x = rtf(o[nt][2] * inv_hi); hi.y = rtf(o[nt][3] * inv_hi);
        *(float2*)&Out[((size_t)b * S_ + row_lo) * HID_ + col]     = lo;
        *(float2*)&Out[((size_t)b * S_ + row_lo + 8) * HID_ + col] = hi;
    }
}

// ---------------- launch ----------------------------------------------------
extern "C" void kernel_launch(void* const* d_in, const int* in_sizes, int n_in,
                              void* d_out, int out_size) {
    const float* hidden  = (const float*)d_in[0];
    const float* w_qkv   = (const float*)d_in[1];
    const float* w_dense = (const float*)d_in[2];
    const float* b_dense = (const float*)d_in[3];
    float* out = (float*)d_out;

    void *p_qkv, *p_attno, *p_hid, *p_wqkv, *p_wdense;
    cudaGetSymbolAddress(&p_qkv, g_qkv);
    cudaGetSymbolAddress(&p_attno, g_attno);
    cudaGetSymbolAddress(&p_hid, g_hid_r);
    cudaGetSymbolAddress(&p_wqkv, g_wqkv_r);
    cudaGetSymbolAddress(&p_wdense, g_wdense_r);

    rope_table_kernel<<<(S_ * HD_ + 255) / 256, 256>>>();

    // pre-round inputs to tf32 (bandwidth-bound, ~15us)
    round_tf32_kernel<<<(M_ * HID_ / 4 + 255) / 256, 256>>>(hidden, (float*)p_hid, M_ * HID_ / 4);
    round_tf32_kernel<<<(HID_ * QKV_N / 4 + 255) / 256, 256>>>(w_qkv, (float*)p_wqkv, HID_ * QKV_N / 4);
    round_tf32_kernel<<<(HID_ * HID_ / 4 + 255) / 256, 256>>>(w_dense, (float*)p_wdense, HID_ * HID_ / 4);

    size_t gemm_smem = (size_t)(2 * ASZ + 2 * BSZ) * sizeof(float);   // 71680
    cudaFuncSetAttribute(gemm_tc, cudaFuncAttributeMaxDynamicSharedMemorySize,
                         (int)gemm_smem);

    {
        dim3 grid(QKV_N / 128, M_ / 128);
        gemm_tc<<<grid, 256, gemm_smem>>>((const float*)p_hid, (const float*)p_wqkv,
                                          nullptr, (float*)p_qkv,
                                          M_, QKV_N, HID_, 0);
    }

    qkv_transform_kernel<<<(B_ * NH_ * S_ * HD_) / 256, 256>>>();

    {
        size_t smem = (size_t)(2 * KSZ + 2 * VSZ) * sizeof(float);    // 71680
        cudaFuncSetAttribute(attn_tc, cudaFuncAttributeMaxDynamicSharedMemorySize,
                             (int)smem);
        dim3 grid(S_ / 128, B_ * NH_);
        attn_tc<<<grid, 256, smem>>>((float*)p_attno);
    }

    {
        dim3 grid(HID_ / 128, M_ / 128);
        gemm_tc<<<grid, 256, gemm_smem>>>((const float*)p_attno, (const float*)p_wdense,
                                          b_dense, out, M_, HID_, HID_, 0);
    }
}

// round 4
// speedup vs baseline: 3.0451x; 1.0208x over previous
#include <cuda_runtime.h>
#include <cuda_bf16.h>
#include <math.h>

#define B_   2
#define S_   2048
#define HID_ 1024
#define NH_  16
#define HD_  64
#define M_   (B_ * S_)        // 4096
#define QKV_N (3 * HID_)      // 3072

// ---------------- scratch (device globals) ---------------------------------
__device__ float g_q[B_ * NH_ * S_ * HD_];     // [b,h,s,dperm] tf32, pre-scaled
__device__ float g_k[B_ * NH_ * S_ * HD_];     // [b,h,s,dperm] tf32
__device__ float g_v[B_ * NH_ * S_ * HD_];     // [b,h,s,d]     tf32
__device__ float g_attno[M_ * HID_];           // [b,s, col-perm] tf32
__device__ float g_cos[S_ * HD_];
__device__ float g_sin[S_ * HD_];
__device__ float g_hid_r[M_ * HID_];           // tf32, col-perm
__device__ float g_wqkv_r[HID_ * QKV_N];       // tf32, plain
__device__ float g_wdense_r[HID_ * HID_];      // tf32, plain

// ---------------- helpers ---------------------------------------------------
__device__ __forceinline__ unsigned f2tf(float x) {
    unsigned r;
    asm("cvt.rna.tf32.f32 %0, %1;" : "=r"(r) : "f"(x));
    return r;
}
__device__ __forceinline__ float rtf(float x) { return __uint_as_float(f2tf(x)); }
__device__ __forceinline__ float ex2(float x) {
    float r;
    asm("ex2.approx.f32 %0, %1;" : "=f"(r) : "f"(x));
    return r;
}
__device__ __forceinline__ void mma_tf32(float* c, const unsigned* a,
                                         unsigned b0, unsigned b1) {
    asm volatile(
        "mma.sync.aligned.m16n8k8.row.col.f32.tf32.tf32.f32 "
        "{%0,%1,%2,%3}, {%4,%5,%6,%7}, {%8,%9}, {%0,%1,%2,%3};\n"
        : "+f"(c[0]), "+f"(c[1]), "+f"(c[2]), "+f"(c[3])
        : "r"(a[0]), "r"(a[1]), "r"(a[2]), "r"(a[3]), "r"(b0), "r"(b1));
}
__device__ __forceinline__ void cp_async16(void* smem, const void* gmem) {
    unsigned s = (unsigned)__cvta_generic_to_shared(smem);
    asm volatile("cp.async.cg.shared.global [%0], [%1], 16;" :: "r"(s), "l"(gmem));
}
#define CP_COMMIT asm volatile("cp.async.commit_group;")
#define CP_WAIT0  asm volatile("cp.async.wait_group 0;")
#define CP_WAIT1  asm volatile("cp.async.wait_group 1;")

// pair-permutation within an 8-group: (k,k+4) become adjacent
__device__ __forceinline__ int dperm(int d) {
    int r = d & 7;
    return (d & ~7) + ((r < 4) ? 2 * r : 2 * (r - 4) + 1);
}

// ---------------- prep kernels ----------------------------------------------
__global__ void round_tf32_kernel(const float* __restrict__ in,
                                  float* __restrict__ out, int n4) {
    int i = blockIdx.x * blockDim.x + threadIdx.x;
    if (i >= n4) return;
    float4 f = ((const float4*)in)[i];
    f.x = rtf(f.x); f.y = rtf(f.y); f.z = rtf(f.z); f.w = rtf(f.w);
    ((float4*)out)[i] = f;
}
// round + column pair-permute (8 floats per thread)
__global__ void round_perm_kernel(const float* __restrict__ in,
                                  float* __restrict__ out, int n8) {
    int i = blockIdx.x * blockDim.x + threadIdx.x;
    if (i >= n8) return;
    float4 a = ((const float4*)in)[2 * i];
    float4 b = ((const float4*)in)[2 * i + 1];
    float4 oa = make_float4(rtf(a.x), rtf(b.x), rtf(a.y), rtf(b.y));
    float4 ob = make_float4(rtf(a.z), rtf(b.z), rtf(a.w), rtf(b.w));
    ((float4*)out)[2 * i]     = oa;
    ((float4*)out)[2 * i + 1] = ob;
}

__global__ void rope_table_kernel() {
    int idx = blockIdx.x * blockDim.x + threadIdx.x;
    if (idx >= S_ * HD_) return;
    int s = idx >> 6;
    int d = idx & 63;
    int i = d & 31;
    double inv = pow(10000.0, -((double)(2 * i)) / (double)HD_);
    float freq = (float)s * (float)inv;
    g_cos[idx] = (float)cos((double)freq);
    g_sin[idx] = (float)sin((double)freq);
}

// ---------------- shared tf32 GEMM mainloop ---------------------------------
// A is column-pair-permuted tf32; W is plain tf32. 128x128x32 tile, 256 thr.
#define ASTR 40
#define BSTR 136
#define ASZ  (128 * ASTR)
#define BSZ  (32 * BSTR)

__device__ __forceinline__ void gemm_main(
    const float* __restrict__ A, const float* __restrict__ W,
    int M, int N, int K, int row0, int col0, float* sm,
    float acc[2][8][4], int tid, int lane, int warp, int wm, int wn)
{
    float* As = sm;               // [2][128][40]
    float* Bs = sm + 2 * ASZ;     // [2][32][136]

#pragma unroll
    for (int mt = 0; mt < 2; mt++)
#pragma unroll
        for (int nt = 0; nt < 8; nt++)
#pragma unroll
            for (int j = 0; j < 4; j++) acc[mt][nt][j] = 0.0f;

    auto load_tiles = [&](int st, int t) {
        int k0 = t * 32;
#pragma unroll
        for (int i = 0; i < 4; i++) {
            int id = tid + i * 256;
            int r = id >> 3, c4 = (id & 7) * 4;
            cp_async16(&As[st * ASZ + r * ASTR + c4],
                       &A[(size_t)(row0 + r) * K + k0 + c4]);
        }
#pragma unroll
        for (int i = 0; i < 4; i++) {
            int id = tid + i * 256;
            int r = id >> 5, n4 = (id & 31) * 4;
            cp_async16(&Bs[st * BSZ + r * BSTR + n4],
                       &W[(size_t)(k0 + r) * N + col0 + n4]);
        }
    };

    int nk = K / 32;
    load_tiles(0, 0);
    CP_COMMIT;

    for (int t = 0; t < nk; t++) {
        int st = t & 1;
        if (t + 1 < nk) { load_tiles(st ^ 1, t + 1); CP_COMMIT; CP_WAIT1; }
        else           { CP_WAIT0; }
        __syncthreads();

        const float*    Ast = As + st * ASZ;
        const unsigned* Bst = (const unsigned*)(Bs + st * BSZ);
#pragma unroll
        for (int ks = 0; ks < 4; ks++) {
            int k0 = ks * 8;
            unsigned a[2][4];
#pragma unroll
            for (int mt = 0; mt < 2; mt++) {
                int m = wm + mt * 16 + (lane >> 2);
                float2 p0 = *(const float2*)&Ast[m * ASTR + k0 + 2 * (lane & 3)];
                float2 p1 = *(const float2*)&Ast[(m + 8) * ASTR + k0 + 2 * (lane & 3)];
                a[mt][0] = __float_as_uint(p0.x);
                a[mt][2] = __float_as_uint(p0.y);
                a[mt][1] = __float_as_uint(p1.x);
                a[mt][3] = __float_as_uint(p1.y);
            }
            unsigned b[8][2];
#pragma unroll
            for (int nt = 0; nt < 8; nt++) {
                int n = wn + nt * 8 + (lane >> 2);
                int k = k0 + (lane & 3);
                b[nt][0] = Bst[k * BSTR + n];
                b[nt][1] = Bst[(k + 4) * BSTR + n];
            }
#pragma unroll
            for (int mt = 0; mt < 2; mt++)
#pragma unroll
                for (int nt = 0; nt < 8; nt++)
                    mma_tf32(acc[mt][nt], a[mt], b[nt][0], b[nt][1]);
        }
        __syncthreads();
    }
}

// ---------------- QKV GEMM with fused RoPE/split/round epilogue -------------
__global__ __launch_bounds__(256, 2)
void gemm_qkv(const float* __restrict__ A, const float* __restrict__ W) {
    extern __shared__ float sm[];
    int tid  = threadIdx.x;
    int lane = tid & 31;
    int warp = tid >> 5;
    int row0 = blockIdx.y * 128;
    int col0 = blockIdx.x * 128;
    int wm = (warp & 3) * 32;
    int wn = (warp >> 2) * 64;

    float acc[2][8][4];
    gemm_main(A, W, M_, QKV_N, HID_, row0, col0, sm, acc, tid, lane, warp, wm, wn);

    int region   = col0 >> 10;                 // 0=q 1=k 2=v
    int colbase  = (col0 & 1023) + wn;
    int h        = colbase >> 6;
    const float QS = 0.125f * 1.4426950408889634f;   // 1/sqrt(64) * log2(e)

#pragma unroll
    for (int mt = 0; mt < 2; mt++) {
        int r  = row0 + wm + mt * 16 + (lane >> 2);
        int b  = r >> 11;
        int sI = r & 2047;
        size_t base_lo = ((size_t)((b << 4) + h) * S_ + sI) * 64;
        size_t base_hi = base_lo + 8 * 64;

        if (region == 2) {
#pragma unroll
            for (int nt = 0; nt < 8; nt++) {
                int d = nt * 8 + 2 * (lane & 3);
                float2 lo, hi;
                lo.x = rtf(acc[mt][nt][0]); lo.y = rtf(acc[mt][nt][1]);
                hi.x = rtf(acc[mt][nt][2]); hi.y = rtf(acc[mt][nt][3]);
                *(float2*)&g_v[base_lo + d] = lo;
                *(float2*)&g_v[base_hi + d] = hi;
            }
        } else {
            float* dst = (region == 0) ? g_q : g_k;
            float SC   = (region == 0) ? QS : 1.0f;
#pragma unroll
            for (int nt = 0; nt < 4; nt++) {
                int d = nt * 8 + 2 * (lane & 3);    // d < 32
                float c0  = g_cos[sI * 64 + d],       c1  = g_cos[sI * 64 + d + 1];
                float s0  = g_sin[sI * 64 + d],       s1  = g_sin[sI * 64 + d + 1];
                float c0h = g_cos[(sI + 8) * 64 + d], c1h = g_cos[(sI + 8) * 64 + d + 1];
                float s0h = g_sin[(sI + 8) * 64 + d], s1h = g_sin[(sI + 8) * 64 + d + 1];

                float x0 = acc[mt][nt][0],     x1 = acc[mt][nt][1];
                float x2 = acc[mt][nt][2],     x3 = acc[mt][nt][3];
                float y0 = acc[mt][nt + 4][0], y1 = acc[mt][nt + 4][1];
                float y2 = acc[mt][nt + 4][2], y3 = acc[mt][nt + 4][3];

                int pd  = dperm(d);
                int pd1 = dperm(d + 1);
                int pD  = dperm(d + 32);
                int pD1 = dperm(d + 33);

                dst[base_lo + pd]  = rtf((x0 * c0  - y0 * s0 ) * SC);
                dst[base_lo + pd1] = rtf((x1 * c1  - y1 * s1 ) * SC);
                dst[base_lo + pD]  = rtf((y0 * c0  + x0 * s0 ) * SC);
                dst[base_lo + pD1] = rtf((y1 * c1  + x1 * s1 ) * SC);
                dst[base_hi + pd]  = rtf((x2 * c0h - y2 * s0h) * SC);
                dst[base_hi + pd1] = rtf((x3 * c1h - y3 * s1h) * SC);
                dst[base_hi + pD]  = rtf((y2 * c0h + x2 * s0h) * SC);
                dst[base_hi + pD1] = rtf((y3 * c1h + x3 * s1h) * SC);
            }
        }
    }
}

// ---------------- dense GEMM (plain output + bias) ---------------------------
__global__ __launch_bounds__(256, 2)
void gemm_dense(const float* __restrict__ A, const float* __restrict__ W,
                const float* __restrict__ bias, float* __restrict__ C) {
    extern __shared__ float sm[];
    int tid  = threadIdx.x;
    int lane = tid & 31;
    int warp = tid >> 5;
    int row0 = blockIdx.y * 128;
    int col0 = blockIdx.x * 128;
    int wm = (warp & 3) * 32;
    int wn = (warp >> 2) * 64;

    float acc[2][8][4];
    gemm_main(A, W, M_, HID_, HID_, row0, col0, sm, acc, tid, lane, warp, wm, wn);

#pragma unroll
    for (int mt = 0; mt < 2; mt++) {
        int r = row0 + wm + mt * 16 + (lane >> 2);
#pragma unroll
        for (int nt = 0; nt < 8; nt++) {
            int c = col0 + wn + nt * 8 + 2 * (lane & 3);
            float bx = bias[c], by = bias[c + 1];
            float2 lo, hi;
            lo.x = acc[mt][nt][0] + bx; lo.y = acc[mt][nt][1] + by;
            hi.x = acc[mt][nt][2] + bx; hi.y = acc[mt][nt][3] + by;
            *(float2*)&C[(size_t)r * HID_ + c]       = lo;
            *(float2*)&C[(size_t)(r + 8) * HID_ + c] = hi;
        }
    }
}

// ---------------- causal flash attention (tf32 mma) --------------------------
#define KSTR 72
#define VSTR 72
#define KSZ  (64 * KSTR)
#define VSZ  (64 * VSTR)

__global__ __launch_bounds__(256, 2)
void attn_tc(float* __restrict__ Out) {
    extern __shared__ float sm[];
    float* Ks = sm;               // [2][64][72]  (pair-interleaved d)
    float* Vs = sm + 2 * KSZ;     // [2][64][72]  (plain)

    int qblk = gridDim.x - 1 - blockIdx.x;
    int bh   = blockIdx.y;
    int qb   = qblk * 128;
    int qt2  = qblk * 2;
    int b = bh >> 4, h = bh & 15;

    const float* Qb = g_q + (size_t)bh * S_ * HD_;
    const float* Kb = g_k + (size_t)bh * S_ * HD_;
    const float* Vb = g_v + (size_t)bh * S_ * HD_;

    int tid  = threadIdx.x;
    int lane = tid & 31;
    int warp = tid >> 5;
    int row_lo = qb + warp * 16 + (lane >> 2);

    // Q fragments via paired LDG.64 (g_q is pair-interleaved + pre-scaled)
    unsigned qf[8][4];
#pragma unroll
    for (int ks = 0; ks < 8; ks++) {
        float2 p0 = *(const float2*)&Qb[(size_t)row_lo * 64 + ks * 8 + 2 * (lane & 3)];
        float2 p1 = *(const float2*)&Qb[(size_t)(row_lo + 8) * 64 + ks * 8 + 2 * (lane & 3)];
        qf[ks][0] = __float_as_uint(p0.x);
        qf[ks][2] = __float_as_uint(p0.y);
        qf[ks][1] = __float_as_uint(p1.x);
        qf[ks][3] = __float_as_uint(p1.y);
    }

    float o[8][4];
#pragma unroll
    for (int nt = 0; nt < 8; nt++)
#pragma unroll
        for (int j = 0; j < 4; j++) o[nt][j] = 0.0f;
    float m_lo = -1e30f, m_hi = -1e30f, l_lo = 0.0f, l_hi = 0.0f;

    auto load_kv = [&](int st, int kt) {
#pragma unroll
        for (int i = 0; i < 4; i++) {
            int id = tid + i * 256;
            int r = id >> 4, d4 = (id & 15) * 4;
            cp_async16(&Ks[st * KSZ + r * KSTR + d4],
                       &Kb[(size_t)(kt * 64 + r) * 64 + d4]);
            cp_async16(&Vs[st * VSZ + r * VSTR + d4],
                       &Vb[(size_t)(kt * 64 + r) * 64 + d4]);
        }
    };

    int nkt = qt2 + 2;
    load_kv(0, 0);
    CP_COMMIT;

    for (int kt = 0; kt < nkt; kt++) {
        int st = kt & 1;
        if (kt + 1 < nkt) { load_kv(st ^ 1, kt + 1); CP_COMMIT; CP_WAIT1; }
        else              { CP_WAIT0; }
        __syncthreads();

        if (kt * 64 <= qb + warp * 16 + 15) {
            const float*    Kst = Ks + st * KSZ;
            const unsigned* Vst = (const unsigned*)(Vs + st * VSZ);

            // S = Q @ K^T  (B-frag pairs via one LDS.64 each)
            float s[8][4];
#pragma unroll
            for (int nt = 0; nt < 8; nt++)
#pragma unroll
                for (int j = 0; j < 4; j++) s[nt][j] = 0.0f;

#pragma unroll
            for (int ks = 0; ks < 8; ks++) {
                int koff = ks * 8 + 2 * (lane & 3);
#pragma unroll
                for (int nt = 0; nt < 8; nt++) {
                    int tok = nt * 8 + (lane >> 2);
                    float2 bb = *(const float2*)&Kst[tok * KSTR + koff];
                    mma_tf32(s[nt], qf[ks],
                             __float_as_uint(bb.x), __float_as_uint(bb.y));
                }
            }

            // causal mask (scores are in log2 units; -1e30 still dominates)
            if (kt >= qt2) {
#pragma unroll
                for (int nt = 0; nt < 8; nt++) {
                    int key0 = kt * 64 + nt * 8 + 2 * (lane & 3);
                    if (key0     > row_lo)     s[nt][0] = -1e30f;
                    if (key0 + 1 > row_lo)     s[nt][1] = -1e30f;
                    if (key0     > row_lo + 8) s[nt][2] = -1e30f;
                    if (key0 + 1 > row_lo + 8) s[nt][3] = -1e30f;
                }
            }

            // online softmax in exp2 domain
            float mloc_lo = -1e30f, mloc_hi = -1e30f;
#pragma unroll
            for (int nt = 0; nt < 8; nt++) {
                mloc_lo = fmaxf(mloc_lo, fmaxf(s[nt][0], s[nt][1]));
                mloc_hi = fmaxf(mloc_hi, fmaxf(s[nt][2], s[nt][3]));
            }
            mloc_lo = fmaxf(mloc_lo, __shfl_xor_sync(0xffffffffu, mloc_lo, 1));
            mloc_lo = fmaxf(mloc_lo, __shfl_xor_sync(0xffffffffu, mloc_lo, 2));
            mloc_hi = fmaxf(mloc_hi, __shfl_xor_sync(0xffffffffu, mloc_hi, 1));
            mloc_hi = fmaxf(mloc_hi, __shfl_xor_sync(0xffffffffu, mloc_hi, 2));

            float mn_lo = fmaxf(m_lo, mloc_lo);
            float mn_hi = fmaxf(m_hi, mloc_hi);
            float scl_lo = ex2(m_lo - mn_lo);
            float scl_hi = ex2(m_hi - mn_hi);
            m_lo = mn_lo; m_hi = mn_hi;

            float lloc_lo = 0.0f, lloc_hi = 0.0f;
#pragma unroll
            for (int nt = 0; nt < 8; nt++) {
                s[nt][0] = ex2(s[nt][0] - m_lo);
                s[nt][1] = ex2(s[nt][1] - m_lo);
                s[nt][2] = ex2(s[nt][2] - m_hi);
                s[nt][3] = ex2(s[nt][3] - m_hi);
                lloc_lo += s[nt][0] + s[nt][1];
                lloc_hi += s[nt][2] + s[nt][3];
            }
            lloc_lo += __shfl_xor_sync(0xffffffffu, lloc_lo, 1);
            lloc_lo += __shfl_xor_sync(0xffffffffu, lloc_lo, 2);
            lloc_hi += __shfl_xor_sync(0xffffffffu, lloc_hi, 1);
            lloc_hi += __shfl_xor_sync(0xffffffffu, lloc_hi, 2);
            l_lo = l_lo * scl_lo + lloc_lo;
            l_hi = l_hi * scl_hi + lloc_hi;

#pragma unroll
            for (int nt = 0; nt < 8; nt++) {
                o[nt][0] *= scl_lo; o[nt][1] *= scl_lo;
                o[nt][2] *= scl_hi; o[nt][3] *= scl_hi;
            }

            // P (C-layout) -> A fragments via shuffles, then O += P @ V
            int lane_lo = (lane & ~3) | ((lane & 3) >> 1);
            int lane_hi = lane_lo + 2;
            int sel = lane & 1;
#pragma unroll
            for (int kt2 = 0; kt2 < 8; kt2++) {
                float v0, v1;
                v0 = __shfl_sync(0xffffffffu, s[kt2][0], lane_lo);
                v1 = __shfl_sync(0xffffffffu, s[kt2][1], lane_lo);
                float p0 = sel ? v1 : v0;
                v0 = __shfl_sync(0xffffffffu, s[kt2][2], lane_lo);
                v1 = __shfl_sync(0xffffffffu, s[kt2][3], lane_lo);
                float p1 = sel ? v1 : v0;
                v0 = __shfl_sync(0xffffffffu, s[kt2][0], lane_hi);
                v1 = __shfl_sync(0xffffffffu, s[kt2][1], lane_hi);
                float p2 = sel ? v1 : v0;
                v0 = __shfl_sync(0xffffffffu, s[kt2][2], lane_hi);
                v1 = __shfl_sync(0xffffffffu, s[kt2][3], lane_hi);
                float p3 = sel ? v1 : v0;

                unsigned a[4];
                a[0] = f2tf(p0); a[1] = f2tf(p1);
                a[2] = f2tf(p2); a[3] = f2tf(p3);

                int tok = kt2 * 8 + (lane & 3);
#pragma unroll
                for (int nt = 0; nt < 8; nt++) {
                    int d = nt * 8 + (lane >> 2);
                    unsigned b0 = Vst[tok * VSTR + d];
                    unsigned b1 = Vst[(tok + 4) * VSTR + d];
                    mma_tf32(o[nt], a, b0, b1);
                }
            }
        }
        __syncthreads();
    }

    // write rounded + column-pair-permuted output (feeds dense GEMM A)
    float inv_lo = 1.0f / l_lo;
    float inv_hi = 1.0f / l_hi;
    int j  = lane & 3;
    int p0 = (j < 2) ? 4 * j     : 4 * j - 7;
    int p1 = (j < 2) ? 4 * j + 2 : 4 * j - 5;
    size_t rb_lo = ((size_t)b * S_ + row_lo) * HID_;
    size_t rb_hi = ((size_t)b * S_ + row_lo + 8) * HID_;
#pragma unroll
    for (int nt = 0; nt < 8; nt++) {
        int cb = h * 64 + nt * 8;
        Out[rb_lo + cb + p0] = rtf(o[nt][0] * inv_lo);
        Out[rb_lo + cb + p1] = rtf(o[nt][1] * inv_lo);
        Out[rb_hi + cb + p0] = rtf(o[nt][2] * inv_hi);
        Out[rb_hi + cb + p1] = rtf(o[nt][3] * inv_hi);
    }
}

// ---------------- launch ----------------------------------------------------
extern "C" void kernel_launch(void* const* d_in, const int* in_sizes, int n_in,
                              void* d_out, int out_size) {
    const float* hidden  = (const float*)d_in[0];
    const float* w_qkv   = (const float*)d_in[1];
    const float* w_dense = (const float*)d_in[2];
    const float* b_dense = (const float*)d_in[3];
    float* out = (float*)d_out;

    void *p_attno, *p_hid, *p_wqkv, *p_wdense;
    cudaGetSymbolAddress(&p_attno, g_attno);
    cudaGetSymbolAddress(&p_hid, g_hid_r);
    cudaGetSymbolAddress(&p_wqkv, g_wqkv_r);
    cudaGetSymbolAddress(&p_wdense, g_wdense_r);

    rope_table_kernel<<<(S_ * HD_ + 255) / 256, 256>>>();

    round_perm_kernel<<<(M_ * HID_ / 8 + 255) / 256, 256>>>(hidden, (float*)p_hid,
                                                            M_ * HID_ / 8);
    round_tf32_kernel<<<(HID_ * QKV_N / 4 + 255) / 256, 256>>>(w_qkv, (float*)p_wqkv,
                                                               HID_ * QKV_N / 4);
    round_tf32_kernel<<<(HID_ * HID_ / 4 + 255) / 256, 256>>>(w_dense, (float*)p_wdense,
                                                              HID_ * HID_ / 4);

    size_t gemm_smem = (size_t)(2 * ASZ + 2 * BSZ) * sizeof(float);   // 75776
    cudaFuncSetAttribute(gemm_qkv, cudaFuncAttributeMaxDynamicSharedMemorySize,
                         (int)gemm_smem);
    cudaFuncSetAttribute(gemm_dense, cudaFuncAttributeMaxDynamicSharedMemorySize,
                         (int)gemm_smem);

    {
        dim3 grid(QKV_N / 128, M_ / 128);
        gemm_qkv<<<grid, 256, gemm_smem>>>((const float*)p_hid, (const float*)p_wqkv);
    }

    {
        size_t smem = (size_t)(2 * KSZ + 2 * VSZ) * sizeof(float);    // 73728
        cudaFuncSetAttribute(attn_tc, cudaFuncAttributeMaxDynamicSharedMemorySize,
                             (int)smem);
        dim3 grid(S_ / 128, B_ * NH_);
        attn_tc<<<grid, 256, smem>>>((float*)p_attno);
    }

    {
        dim3 grid(HID_ / 128, M_ / 128);
        gemm_dense<<<grid, 256, gemm_smem>>>((const float*)p_attno,
                                             (const float*)p_wdense, b_dense, out);
    }
}

// round 6
// speedup vs baseline: 5.2540x; 1.7254x over previous
#include <cuda_runtime.h>
#include <cuda_fp16.h>
#include <math.h>

#define B_   2
#define S_   2048
#define HID_ 1024
#define NH_  16
#define HD_  64
#define M_   (B_ * S_)        // 4096
#define QKV_N (3 * HID_)      // 3072

// ---------------- scratch (device globals) ---------------------------------
__device__ __half g_q[B_ * NH_ * S_ * HD_];    // [b,h,s,d] fp16, pre-scaled
__device__ __half g_k[B_ * NH_ * S_ * HD_];    // [b,h,s,d] fp16
__device__ __half g_v[B_ * NH_ * S_ * HD_];    // [b,h,s,d] fp16
__device__ __half g_attno[M_ * HID_];          // [b,s,hid] fp16
__device__ float  g_cos[S_ * HD_];
__device__ float  g_sin[S_ * HD_];
__device__ __half g_hid_h[M_ * HID_];          // fp16 plain
__device__ __half g_wqkv_t[QKV_N * HID_];      // [N,K] fp16 (transposed)
__device__ __half g_wdense_t[HID_ * HID_];     // [N,K] fp16 (transposed)

// ---------------- helpers ---------------------------------------------------
__device__ __forceinline__ float ex2(float x) {
    float r;
    asm("ex2.approx.f32 %0, %1;" : "=f"(r) : "f"(x));
    return r;
}
__device__ __forceinline__ unsigned packh2(float a, float b) {
    __half2 h = __floats2half2_rn(a, b);
    return *(unsigned*)&h;
}
__device__ __forceinline__ void mma_f16(float* c, const unsigned* a,
                                        unsigned b0, unsigned b1) {
    asm volatile(
        "mma.sync.aligned.m16n8k16.row.col.f32.f16.f16.f32 "
        "{%0,%1,%2,%3}, {%4,%5,%6,%7}, {%8,%9}, {%0,%1,%2,%3};\n"
        : "+f"(c[0]), "+f"(c[1]), "+f"(c[2]), "+f"(c[3])
        : "r"(a[0]), "r"(a[1]), "r"(a[2]), "r"(a[3]), "r"(b0), "r"(b1));
}
__device__ __forceinline__ void ldsm_x4(unsigned* r, unsigned saddr) {
    asm volatile("ldmatrix.sync.aligned.m8n8.x4.shared.b16 {%0,%1,%2,%3}, [%4];"
                 : "=r"(r[0]), "=r"(r[1]), "=r"(r[2]), "=r"(r[3]) : "r"(saddr));
}
__device__ __forceinline__ void ldsm_x4_t(unsigned* r, unsigned saddr) {
    asm volatile("ldmatrix.sync.aligned.m8n8.x4.trans.shared.b16 {%0,%1,%2,%3}, [%4];"
                 : "=r"(r[0]), "=r"(r[1]), "=r"(r[2]), "=r"(r[3]) : "r"(saddr));
}
__device__ __forceinline__ void cp16s(unsigned saddr, const void* gmem) {
    asm volatile("cp.async.cg.shared.global [%0], [%1], 16;" :: "r"(saddr), "l"(gmem));
}
#define CP_COMMIT asm volatile("cp.async.commit_group;")
#define CP_WAIT0  asm volatile("cp.async.wait_group 0;")
#define CP_WAIT1  asm volatile("cp.async.wait_group 1;")

// ---------------- prep kernels ----------------------------------------------
__global__ void f2h_kernel(const float* __restrict__ in,
                           __half* __restrict__ out, int n4) {
    int i = blockIdx.x * blockDim.x + threadIdx.x;
    if (i >= n4) return;
    float4 f = ((const float4*)in)[i];
    ((uint2*)out)[i] = make_uint2(packh2(f.x, f.y), packh2(f.z, f.w));
}
// out[c][r] = half(in[r][c]); in is [R][C] fp32
__global__ void transpose_h_kernel(const float* __restrict__ in,
                                   __half* __restrict__ out, int R, int C) {
    __shared__ float t[32][33];
    int rb = blockIdx.y * 32, cb = blockIdx.x * 32;
    int tx = threadIdx.x, ty = threadIdx.y;
#pragma unroll
    for (int i = ty; i < 32; i += 8)
        t[i][tx] = in[(size_t)(rb + i) * C + cb + tx];
    __syncthreads();
#pragma unroll
    for (int i = ty; i < 32; i += 8)
        out[(size_t)(cb + i) * R + rb + tx] = __float2half_rn(t[tx][i]);
}

__global__ void rope_table_kernel() {
    int idx = blockIdx.x * blockDim.x + threadIdx.x;
    if (idx >= S_ * HD_) return;
    int s = idx >> 6;
    int d = idx & 63;
    int i = d & 31;
    double inv = pow(10000.0, -((double)(2 * i)) / (double)HD_);
    float freq = (float)s * (float)inv;
    g_cos[idx] = (float)cos((double)freq);
    g_sin[idx] = (float)sin((double)freq);
}

// ---------------- fp16 GEMM mainloop -----------------------------------------
// C = A[M,1024] @ Wt[N,1024]^T. 128x128x32 tiles, 256 thr (8 warps, 32x64).
// smem rows: 32 halfs data in 80B stride (bank-conflict-free for ldmatrix).
#define GROW 80                     // bytes per smem row
#define GBUF (128 * GROW)           // 10240 bytes per tile buffer

__device__ __forceinline__ void gemm16_main(
    const __half* __restrict__ A, const __half* __restrict__ Wt,
    int row0, int col0, unsigned smem_base, float acc[2][8][4],
    int tid, int lane, int wm, int wn)
{
#pragma unroll
    for (int mt = 0; mt < 2; mt++)
#pragma unroll
        for (int nt = 0; nt < 8; nt++)
#pragma unroll
            for (int j = 0; j < 4; j++) acc[mt][nt][j] = 0.0f;

    auto load_tile = [&](int st, int t) {
        int k0 = t * 32;
        unsigned sa = smem_base + st * GBUF;
        unsigned sb = smem_base + 2 * GBUF + st * GBUF;
#pragma unroll
        for (int it = 0; it < 2; it++) {
            int id = tid + it * 256;          // 0..511
            int r = id >> 2, ch = id & 3;
            cp16s(sa + r * GROW + ch * 16,
                  &A[(size_t)(row0 + r) * HID_ + k0 + ch * 8]);
        }
#pragma unroll
        for (int it = 0; it < 2; it++) {
            int id = tid + it * 256;
            int r = id >> 2, ch = id & 3;
            cp16s(sb + r * GROW + ch * 16,
                  &Wt[(size_t)(col0 + r) * HID_ + k0 + ch * 8]);
        }
    };

    load_tile(0, 0); CP_COMMIT;

    for (int t = 0; t < 32; t++) {
        int st = t & 1;
        if (t + 1 < 32) { load_tile(st ^ 1, t + 1); CP_COMMIT; CP_WAIT1; }
        else            { CP_WAIT0; }
        __syncthreads();

        unsigned sa = smem_base + st * GBUF;
        unsigned sb = smem_base + 2 * GBUF + st * GBUF;
#pragma unroll
        for (int ks = 0; ks < 2; ks++) {
            unsigned a[2][4];
#pragma unroll
            for (int mt = 0; mt < 2; mt++) {
                unsigned addr = sa + (wm + mt * 16 + (lane & 15)) * GROW
                              + ks * 32 + (lane >> 4) * 16;
                ldsm_x4(a[mt], addr);
            }
            unsigned b[8][2];
#pragma unroll
            for (int ntp = 0; ntp < 4; ntp++) {
                int nrow = wn + ntp * 16 + (lane & 7) + ((lane >> 4) << 3);
                unsigned addr = sb + nrow * GROW + ks * 32 + ((lane >> 3) & 1) * 16;
                unsigned r[4];
                ldsm_x4(r, addr);
                b[2 * ntp][0]     = r[0]; b[2 * ntp][1]     = r[1];
                b[2 * ntp + 1][0] = r[2]; b[2 * ntp + 1][1] = r[3];
            }
#pragma unroll
            for (int mt = 0; mt < 2; mt++)
#pragma unroll
                for (int nt = 0; nt < 8; nt++)
                    mma_f16(acc[mt][nt], a[mt], b[nt][0], b[nt][1]);
        }
        __syncthreads();
    }
}

// ---------------- QKV GEMM + fused RoPE/split epilogue ----------------------
__global__ __launch_bounds__(256, 2)
void gemm16_qkv(const __half* __restrict__ A, const __half* __restrict__ Wt) {
    extern __shared__ char dsm[];
    unsigned smem_base = (unsigned)__cvta_generic_to_shared(dsm);
    int tid = threadIdx.x, lane = tid & 31, warp = tid >> 5;
    int row0 = blockIdx.y * 128;
    int col0 = blockIdx.x * 128;
    int wm = (warp & 3) * 32;
    int wn = (warp >> 2) * 64;

    float acc[2][8][4];
    gemm16_main(A, Wt, row0, col0, smem_base, acc, tid, lane, wm, wn);

    int region = col0 >> 10;                 // 0=q 1=k 2=v
    int h      = ((col0 & 1023) + wn) >> 6;  // warp covers one head
    const float QS = 0.125f * 1.4426950408889634f;

#pragma unroll
    for (int mt = 0; mt < 2; mt++) {
        int r = row0 + wm + mt * 16 + (lane >> 2);
        int b = r >> 11, s = r & 2047;
        size_t base_lo = ((size_t)((b << 4) + h) * S_ + s) * 64;
        size_t base_hi = base_lo + 8 * 64;

        if (region == 2) {
#pragma unroll
            for (int nt = 0; nt < 8; nt++) {
                int d = nt * 8 + 2 * (lane & 3);
                *(unsigned*)&g_v[base_lo + d] = packh2(acc[mt][nt][0], acc[mt][nt][1]);
                *(unsigned*)&g_v[base_hi + d] = packh2(acc[mt][nt][2], acc[mt][nt][3]);
            }
        } else {
            __half* dst = (region == 0) ? g_q : g_k;
            float SC    = (region == 0) ? QS : 1.0f;
#pragma unroll
            for (int nt = 0; nt < 4; nt++) {
                int d = nt * 8 + 2 * (lane & 3);    // d < 32
                float2 cl = *(const float2*)&g_cos[s * 64 + d];
                float2 sl = *(const float2*)&g_sin[s * 64 + d];
                float2 ch = *(const float2*)&g_cos[(s + 8) * 64 + d];
                float2 sh = *(const float2*)&g_sin[(s + 8) * 64 + d];

                float x0 = acc[mt][nt][0],     x1 = acc[mt][nt][1];
                float x2 = acc[mt][nt][2],     x3 = acc[mt][nt][3];
                float y0 = acc[mt][nt + 4][0], y1 = acc[mt][nt + 4][1];
                float y2 = acc[mt][nt + 4][2], y3 = acc[mt][nt + 4][3];

                *(unsigned*)&dst[base_lo + d] =
                    packh2((x0 * cl.x - y0 * sl.x) * SC, (x1 * cl.y - y1 * sl.y) * SC);
                *(unsigned*)&dst[base_lo + d + 32] =
                    packh2((y0 * cl.x + x0 * sl.x) * SC, (y1 * cl.y + x1 * sl.y) * SC);
                *(unsigned*)&dst[base_hi + d] =
                    packh2((x2 * ch.x - y2 * sh.x) * SC, (x3 * ch.y - y3 * sh.y) * SC);
                *(unsigned*)&dst[base_hi + d + 32] =
                    packh2((y2 * ch.x + x2 * sh.x) * SC, (y3 * ch.y + x3 * sh.y) * SC);
            }
        }
    }
}

// ---------------- dense GEMM + bias (fp32 out) -------------------------------
__global__ __launch_bounds__(256, 2)
void gemm16_dense(const __half* __restrict__ A, const __half* __restrict__ Wt,
                  const float* __restrict__ bias, float* __restrict__ C) {
    extern __shared__ char dsm[];
    unsigned smem_base = (unsigned)__cvta_generic_to_shared(dsm);
    int tid = threadIdx.x, lane = tid & 31, warp = tid >> 5;
    int row0 = blockIdx.y * 128;
    int col0 = blockIdx.x * 128;
    int wm = (warp & 3) * 32;
    int wn = (warp >> 2) * 64;

    float acc[2][8][4];
    gemm16_main(A, Wt, row0, col0, smem_base, acc, tid, lane, wm, wn);

#pragma unroll
    for (int mt = 0; mt < 2; mt++) {
        int r = row0 + wm + mt * 16 + (lane >> 2);
#pragma unroll
        for (int nt = 0; nt < 8; nt++) {
            int c = col0 + wn + nt * 8 + 2 * (lane & 3);
            float bx = bias[c], by = bias[c + 1];
            float2 lo, hi;
            lo.x = acc[mt][nt][0] + bx; lo.y = acc[mt][nt][1] + by;
            hi.x = acc[mt][nt][2] + bx; hi.y = acc[mt][nt][3] + by;
            *(float2*)&C[(size_t)r * HID_ + c]       = lo;
            *(float2*)&C[(size_t)(r + 8) * HID_ + c] = hi;
        }
    }
}

// ---------------- causal flash attention (fp16 mma + ldmatrix) ---------------
#define AROW 144                    // bytes per smem row (64 halfs data)
#define ABUF (64 * AROW)            // 9216 bytes per tile buffer

__global__ __launch_bounds__(256, 2)
void attn16(__half* __restrict__ Out) {
    extern __shared__ char dsm[];
    unsigned smem_base = (unsigned)__cvta_generic_to_shared(dsm);
    unsigned kb_base = smem_base;              // K: [2][ABUF]
    unsigned vb_base = smem_base + 2 * ABUF;   // V: [2][ABUF]

    int qblk = gridDim.x - 1 - blockIdx.x;     // big blocks first
    int bh   = blockIdx.y;
    int qb   = qblk * 128;
    int b = bh >> 4, h = bh & 15;

    const __half* Qb = g_q + (size_t)bh * S_ * HD_;
    const __half* Kb = g_k + (size_t)bh * S_ * HD_;
    const __half* Vb = g_v + (size_t)bh * S_ * HD_;

    int tid  = threadIdx.x;
    int lane = tid & 31;
    int warp = tid >> 5;
    int row_lo = qb + warp * 16 + (lane >> 2);

    // Q A-fragments (pre-scaled by 1/8*log2e), held in regs for whole loop
    unsigned qf[4][4];
#pragma unroll
    for (int ks = 0; ks < 4; ks++) {
        const __half* qp = Qb + (size_t)row_lo * 64 + ks * 16 + 2 * (lane & 3);
        qf[ks][0] = *(const unsigned*)(qp);
        qf[ks][1] = *(const unsigned*)(qp + 8 * 64);
        qf[ks][2] = *(const unsigned*)(qp + 8);
        qf[ks][3] = *(const unsigned*)(qp + 8 * 64 + 8);
    }

    float o[8][4];
#pragma unroll
    for (int nt = 0; nt < 8; nt++)
#pragma unroll
        for (int j = 0; j < 4; j++) o[nt][j] = 0.0f;
    float m_lo = -1e30f, m_hi = -1e30f, l_lo = 0.0f, l_hi = 0.0f;

    auto load_kv = [&](int st, int kt) {
#pragma unroll
        for (int it = 0; it < 2; it++) {
            int id = tid + it * 256;          // 0..511
            int r = id >> 3, ch = id & 7;
            cp16s(kb_base + st * ABUF + r * AROW + ch * 16,
                  &Kb[(size_t)(kt * 64 + r) * 64 + ch * 8]);
            cp16s(vb_base + st * ABUF + r * AROW + ch * 16,
                  &Vb[(size_t)(kt * 64 + r) * 64 + ch * 8]);
        }
    };

    int qt2 = qblk * 2;
    int nkt = qt2 + 2;
    load_kv(0, 0);
    CP_COMMIT;

    for (int kt = 0; kt < nkt; kt++) {
        int st = kt & 1;
        if (kt + 1 < nkt) { load_kv(st ^ 1, kt + 1); CP_COMMIT; CP_WAIT1; }
        else              { CP_WAIT0; }
        __syncthreads();

        if (kt * 64 <= qb + warp * 16 + 15) {
            unsigned kst = kb_base + st * ABUF;
            unsigned vst = vb_base + st * ABUF;

            // S = Q @ K^T
            float s[8][4];
#pragma unroll
            for (int nt = 0; nt < 8; nt++)
#pragma unroll
                for (int j = 0; j < 4; j++) s[nt][j] = 0.0f;

#pragma unroll
            for (int ks = 0; ks < 4; ks++) {
#pragma unroll
                for (int ntp = 0; ntp < 4; ntp++) {
                    int trow = ntp * 16 + (lane & 7) + ((lane >> 4) << 3);
                    unsigned addr = kst + trow * AROW + ks * 32 + ((lane >> 3) & 1) * 16;
                    unsigned r[4];
                    ldsm_x4(r, addr);
                    mma_f16(s[2 * ntp],     qf[ks], r[0], r[1]);
                    mma_f16(s[2 * ntp + 1], qf[ks], r[2], r[3]);
                }
            }

            // causal mask (log2 domain)
            if (kt >= qt2) {
#pragma unroll
                for (int nt = 0; nt < 8; nt++) {
                    int key0 = kt * 64 + nt * 8 + 2 * (lane & 3);
                    if (key0     > row_lo)     s[nt][0] = -1e30f;
                    if (key0 + 1 > row_lo)     s[nt][1] = -1e30f;
                    if (key0     > row_lo + 8) s[nt][2] = -1e30f;
                    if (key0 + 1 > row_lo + 8) s[nt][3] = -1e30f;
                }
            }

            // online softmax (exp2 domain)
            float mloc_lo = -1e30f, mloc_hi = -1e30f;
#pragma unroll
            for (int nt = 0; nt < 8; nt++) {
                mloc_lo = fmaxf(mloc_lo, fmaxf(s[nt][0], s[nt][1]));
                mloc_hi = fmaxf(mloc_hi, fmaxf(s[nt][2], s[nt][3]));
            }
            mloc_lo = fmaxf(mloc_lo, __shfl_xor_sync(0xffffffffu, mloc_lo, 1));
            mloc_lo = fmaxf(mloc_lo, __shfl_xor_sync(0xffffffffu, mloc_lo, 2));
            mloc_hi = fmaxf(mloc_hi, __shfl_xor_sync(0xffffffffu, mloc_hi, 1));
            mloc_hi = fmaxf(mloc_hi, __shfl_xor_sync(0xffffffffu, mloc_hi, 2));

            float mn_lo = fmaxf(m_lo, mloc_lo);
            float mn_hi = fmaxf(m_hi, mloc_hi);
            float scl_lo = ex2(m_lo - mn_lo);
            float scl_hi = ex2(m_hi - mn_hi);
            m_lo = mn_lo; m_hi = mn_hi;

            float lloc_lo = 0.0f, lloc_hi = 0.0f;
#pragma unroll
            for (int nt = 0; nt < 8; nt++) {
                s[nt][0] = ex2(s[nt][0] - m_lo);
                s[nt][1] = ex2(s[nt][1] - m_lo);
                s[nt][2] = ex2(s[nt][2] - m_hi);
                s[nt][3] = ex2(s[nt][3] - m_hi);
                lloc_lo += s[nt][0] + s[nt][1];
                lloc_hi += s[nt][2] + s[nt][3];
            }
            lloc_lo += __shfl_xor_sync(0xffffffffu, lloc_lo, 1);
            lloc_lo += __shfl_xor_sync(0xffffffffu, lloc_lo, 2);
            lloc_hi += __shfl_xor_sync(0xffffffffu, lloc_hi, 1);
            lloc_hi += __shfl_xor_sync(0xffffffffu, lloc_hi, 2);
            l_lo = l_lo * scl_lo + lloc_lo;
            l_hi = l_hi * scl_hi + lloc_hi;

#pragma unroll
            for (int nt = 0; nt < 8; nt++) {
                o[nt][0] *= scl_lo; o[nt][1] *= scl_lo;
                o[nt][2] *= scl_hi; o[nt][3] *= scl_hi;
            }

            // O += P @ V   (P: direct C->A repack; V via ldmatrix.trans)
#pragma unroll
            for (int ks = 0; ks < 4; ks++) {     // token group of 16
                unsigned pa[4];
                pa[0] = packh2(s[2 * ks][0],     s[2 * ks][1]);
                pa[1] = packh2(s[2 * ks][2],     s[2 * ks][3]);
                pa[2] = packh2(s[2 * ks + 1][0], s[2 * ks + 1][1]);
                pa[3] = packh2(s[2 * ks + 1][2], s[2 * ks + 1][3]);
#pragma unroll
                for (int ntp = 0; ntp < 4; ntp++) {
                    int trow = ks * 16 + (lane & 7) + ((lane >> 3) & 1) * 8;
                    unsigned addr = vst + trow * AROW + (2 * ntp + (lane >> 4)) * 16;
                    unsigned r[4];
                    ldsm_x4_t(r, addr);
                    mma_f16(o[2 * ntp],     pa, r[0], r[1]);
                    mma_f16(o[2 * ntp + 1], pa, r[2], r[3]);
                }
            }
        }
        __syncthreads();
    }

    // normalize, write fp16 (feeds dense GEMM A)
    float inv_lo = 1.0f / l_lo;
    float inv_hi = 1.0f / l_hi;
    size_t rb_lo = ((size_t)b * S_ + row_lo) * HID_;
    size_t rb_hi = ((size_t)b * S_ + row_lo + 8) * HID_;
#pragma unroll
    for (int nt = 0; nt < 8; nt++) {
        int col = h * 64 + nt * 8 + 2 * (lane & 3);
        *(unsigned*)&Out[rb_lo + col] = packh2(o[nt][0] * inv_lo, o[nt][1] * inv_lo);
        *(unsigned*)&Out[rb_hi + col] = packh2(o[nt][2] * inv_hi, o[nt][3] * inv_hi);
    }
}

// ---------------- launch ----------------------------------------------------
extern "C" void kernel_launch(void* const* d_in, const int* in_sizes, int n_in,
                              void* d_out, int out_size) {
    const float* hidden  = (const float*)d_in[0];
    const float* w_qkv   = (const float*)d_in[1];
    const float* w_dense = (const float*)d_in[2];
    const float* b_dense = (const float*)d_in[3];
    float* out = (float*)d_out;

    void *p_attno, *p_hid, *p_wqkv, *p_wdense;
    cudaGetSymbolAddress(&p_attno, g_attno);
    cudaGetSymbolAddress(&p_hid, g_hid_h);
    cudaGetSymbolAddress(&p_wqkv, g_wqkv_t);
    cudaGetSymbolAddress(&p_wdense, g_wdense_t);

    rope_table_kernel<<<(S_ * HD_ + 255) / 256, 256>>>();

    f2h_kernel<<<(M_ * HID_ / 4 + 255) / 256, 256>>>(hidden, (__half*)p_hid,
                                                     M_ * HID_ / 4);
    {
        dim3 grid(QKV_N / 32, HID_ / 32);
        transpose_h_kernel<<<grid, dim3(32, 8)>>>(w_qkv, (__half*)p_wqkv,
                                                  HID_, QKV_N);
    }
    {
        dim3 grid(HID_ / 32, HID_ / 32);
        transpose_h_kernel<<<grid, dim3(32, 8)>>>(w_dense, (__half*)p_wdense,
                                                  HID_, HID_);
    }

    size_t gsmem = 4 * GBUF;   // 40960
    cudaFuncSetAttribute(gemm16_qkv, cudaFuncAttributeMaxDynamicSharedMemorySize,
                         (int)gsmem);
    cudaFuncSetAttribute(gemm16_dense, cudaFuncAttributeMaxDynamicSharedMemorySize,
                         (int)gsmem);

    {
        dim3 grid(QKV_N / 128, M_ / 128);
        gemm16_qkv<<<grid, 256, gsmem>>>((const __half*)p_hid,
                                         (const __half*)p_wqkv);
    }

    {
        size_t asmem = 4 * ABUF;   // 36864
        cudaFuncSetAttribute(attn16, cudaFuncAttributeMaxDynamicSharedMemorySize,
                             (int)asmem);
        dim3 grid(S_ / 128, B_ * NH_);
        attn16<<<grid, 256, asmem>>>((__half*)p_attno);
    }

    {
        dim3 grid(HID_ / 128, M_ / 128);
        gemm16_dense<<<grid, 256, gsmem>>>((const __half*)p_attno,
                                           (const __half*)p_wdense, b_dense, out);
    }
}

// round 7
// speedup vs baseline: 5.6465x; 1.0747x over previous
#include <cuda_runtime.h>
#include <cuda_fp16.h>
#include <math.h>

#define B_   2
#define S_   2048
#define HID_ 1024
#define NH_  16
#define HD_  64
#define M_   (B_ * S_)        // 4096
#define QKV_N (3 * HID_)      // 3072
#define QKV_TILES (24 * 32)   // 768

// ---------------- scratch (device globals) ---------------------------------
__device__ __half g_q[B_ * NH_ * S_ * HD_];    // [b,h,s,d] fp16, pre-scaled
__device__ __half g_k[B_ * NH_ * S_ * HD_];
__device__ __half g_v[B_ * NH_ * S_ * HD_];
__device__ __half g_attno[M_ * HID_];          // [b,s,hid] fp16
__device__ float  g_cos[S_ * HD_];
__device__ float  g_sin[S_ * HD_];
__device__ __half g_hid_h[M_ * HID_];
__device__ __half g_wqkv_t[QKV_N * HID_];      // [N,K] fp16 (transposed)
__device__ __half g_wdense_t[HID_ * HID_];     // [N,K] fp16 (transposed)
__device__ unsigned g_qkv_ctr;                 // persistent-GEMM ticket

// ---------------- helpers ---------------------------------------------------
__device__ __forceinline__ float ex2(float x) {
    float r;
    asm("ex2.approx.f32 %0, %1;" : "=f"(r) : "f"(x));
    return r;
}
__device__ __forceinline__ unsigned packh2(float a, float b) {
    __half2 h = __floats2half2_rn(a, b);
    return *(unsigned*)&h;
}
__device__ __forceinline__ void mma_f16(float* c, const unsigned* a,
                                        unsigned b0, unsigned b1) {
    asm volatile(
        "mma.sync.aligned.m16n8k16.row.col.f32.f16.f16.f32 "
        "{%0,%1,%2,%3}, {%4,%5,%6,%7}, {%8,%9}, {%0,%1,%2,%3};\n"
        : "+f"(c[0]), "+f"(c[1]), "+f"(c[2]), "+f"(c[3])
        : "r"(a[0]), "r"(a[1]), "r"(a[2]), "r"(a[3]), "r"(b0), "r"(b1));
}
__device__ __forceinline__ void ldsm_x4(unsigned* r, unsigned saddr) {
    asm volatile("ldmatrix.sync.aligned.m8n8.x4.shared.b16 {%0,%1,%2,%3}, [%4];"
                 : "=r"(r[0]), "=r"(r[1]), "=r"(r[2]), "=r"(r[3]) : "r"(saddr));
}
__device__ __forceinline__ void ldsm_x4_t(unsigned* r, unsigned saddr) {
    asm volatile("ldmatrix.sync.aligned.m8n8.x4.trans.shared.b16 {%0,%1,%2,%3}, [%4];"
                 : "=r"(r[0]), "=r"(r[1]), "=r"(r[2]), "=r"(r[3]) : "r"(saddr));
}
__device__ __forceinline__ void cp16s(unsigned saddr, const void* gmem) {
    asm volatile("cp.async.cg.shared.global [%0], [%1], 16;" :: "r"(saddr), "l"(gmem));
}
#define CP_COMMIT asm volatile("cp.async.commit_group;")
#define CP_WAIT0  asm volatile("cp.async.wait_group 0;")
#define CP_WAIT1  asm volatile("cp.async.wait_group 1;")

// ---------------- prep kernels ----------------------------------------------
__global__ void f2h_kernel(const float* __restrict__ in,
                           __half* __restrict__ out, int n4) {
    int i = blockIdx.x * blockDim.x + threadIdx.x;
    if (i >= n4) return;
    float4 f = ((const float4*)in)[i];
    ((uint2*)out)[i] = make_uint2(packh2(f.x, f.y), packh2(f.z, f.w));
}
__global__ void transpose_h_kernel(const float* __restrict__ in,
                                   __half* __restrict__ out, int R, int C) {
    __shared__ float t[32][33];
    int rb = blockIdx.y * 32, cb = blockIdx.x * 32;
    int tx = threadIdx.x, ty = threadIdx.y;
#pragma unroll
    for (int i = ty; i < 32; i += 8)
        t[i][tx] = in[(size_t)(rb + i) * C + cb + tx];
    __syncthreads();
#pragma unroll
    for (int i = ty; i < 32; i += 8)
        out[(size_t)(cb + i) * R + rb + tx] = __float2half_rn(t[tx][i]);
}

__global__ void rope_table_kernel() {
    int idx = blockIdx.x * blockDim.x + threadIdx.x;
    if (idx == 0) g_qkv_ctr = 0;               // reset persistent ticket
    if (idx >= S_ * HD_) return;
    int s = idx >> 6;
    int d = idx & 63;
    int i = d & 31;
    double inv = pow(10000.0, -((double)(2 * i)) / (double)HD_);
    float freq = (float)s * (float)inv;
    g_cos[idx] = (float)cos((double)freq);
    g_sin[idx] = (float)sin((double)freq);
}

// ---------------- fp16 GEMM mainloop -----------------------------------------
#define GROW 80                     // bytes per smem row (32 halfs data)
#define GBUF (128 * GROW)           // 10240 bytes per tile buffer

__device__ __forceinline__ void gemm16_main(
    const __half* __restrict__ A, const __half* __restrict__ Wt,
    int row0, int col0, unsigned smem_base, float acc[2][8][4],
    int tid, int lane, int wm, int wn)
{
#pragma unroll
    for (int mt = 0; mt < 2; mt++)
#pragma unroll
        for (int nt = 0; nt < 8; nt++)
#pragma unroll
            for (int j = 0; j < 4; j++) acc[mt][nt][j] = 0.0f;

    auto load_tile = [&](int st, int t) {
        int k0 = t * 32;
        unsigned sa = smem_base + st * GBUF;
        unsigned sb = smem_base + 2 * GBUF + st * GBUF;
#pragma unroll
        for (int it = 0; it < 2; it++) {
            int id = tid + it * 256;
            int r = id >> 2, ch = id & 3;
            cp16s(sa + r * GROW + ch * 16,
                  &A[(size_t)(row0 + r) * HID_ + k0 + ch * 8]);
        }
#pragma unroll
        for (int it = 0; it < 2; it++) {
            int id = tid + it * 256;
            int r = id >> 2, ch = id & 3;
            cp16s(sb + r * GROW + ch * 16,
                  &Wt[(size_t)(col0 + r) * HID_ + k0 + ch * 8]);
        }
    };

    load_tile(0, 0); CP_COMMIT;

    for (int t = 0; t < 32; t++) {
        int st = t & 1;
        if (t + 1 < 32) { load_tile(st ^ 1, t + 1); CP_COMMIT; CP_WAIT1; }
        else            { CP_WAIT0; }
        __syncthreads();

        unsigned sa = smem_base + st * GBUF;
        unsigned sb = smem_base + 2 * GBUF + st * GBUF;
#pragma unroll
        for (int ks = 0; ks < 2; ks++) {
            unsigned a[2][4];
#pragma unroll
            for (int mt = 0; mt < 2; mt++) {
                unsigned addr = sa + (wm + mt * 16 + (lane & 15)) * GROW
                              + ks * 32 + (lane >> 4) * 16;
                ldsm_x4(a[mt], addr);
            }
            unsigned b[8][2];
#pragma unroll
            for (int ntp = 0; ntp < 4; ntp++) {
                int nrow = wn + ntp * 16 + (lane & 7) + ((lane >> 4) << 3);
                unsigned addr = sb + nrow * GROW + ks * 32 + ((lane >> 3) & 1) * 16;
                unsigned r[4];
                ldsm_x4(r, addr);
                b[2 * ntp][0]     = r[0]; b[2 * ntp][1]     = r[1];
                b[2 * ntp + 1][0] = r[2]; b[2 * ntp + 1][1] = r[3];
            }
#pragma unroll
            for (int mt = 0; mt < 2; mt++)
#pragma unroll
                for (int nt = 0; nt < 8; nt++)
                    mma_f16(acc[mt][nt], a[mt], b[nt][0], b[nt][1]);
        }
        __syncthreads();
    }
}

// ---------------- QKV GEMM (persistent) + fused RoPE/split epilogue ---------
__global__ __launch_bounds__(256, 2)
void gemm16_qkv(const __half* __restrict__ A, const __half* __restrict__ Wt) {
    extern __shared__ char dsm[];
    __shared__ int s_tile;
    unsigned smem_base = (unsigned)__cvta_generic_to_shared(dsm);
    int tid = threadIdx.x, lane = tid & 31, warp = tid >> 5;
    int wm = (warp & 3) * 32;
    int wn = (warp >> 2) * 64;
    const float QS = 0.125f * 1.4426950408889634f;

    for (;;) {
        if (tid == 0) s_tile = (int)atomicAdd(&g_qkv_ctr, 1u);
        __syncthreads();
        int t = s_tile;
        if (t >= QKV_TILES) break;
        int row0 = (t & 31) * 128;
        int col0 = (t >> 5) * 128;

        float acc[2][8][4];
        gemm16_main(A, Wt, row0, col0, smem_base, acc, tid, lane, wm, wn);

        int region = col0 >> 10;                 // 0=q 1=k 2=v
        int h      = ((col0 & 1023) + wn) >> 6;  // warp covers one head

#pragma unroll
        for (int mt = 0; mt < 2; mt++) {
            int r = row0 + wm + mt * 16 + (lane >> 2);
            int b = r >> 11, s = r & 2047;
            size_t base_lo = ((size_t)((b << 4) + h) * S_ + s) * 64;
            size_t base_hi = base_lo + 8 * 64;

            if (region == 2) {
#pragma unroll
                for (int nt = 0; nt < 8; nt++) {
                    int d = nt * 8 + 2 * (lane & 3);
                    *(unsigned*)&g_v[base_lo + d] =
                        packh2(acc[mt][nt][0], acc[mt][nt][1]);
                    *(unsigned*)&g_v[base_hi + d] =
                        packh2(acc[mt][nt][2], acc[mt][nt][3]);
                }
            } else {
                __half* dst = (region == 0) ? g_q : g_k;
                float SC    = (region == 0) ? QS : 1.0f;
#pragma unroll
                for (int nt = 0; nt < 4; nt++) {
                    int d = nt * 8 + 2 * (lane & 3);    // d < 32
                    float2 cl = *(const float2*)&g_cos[s * 64 + d];
                    float2 sl = *(const float2*)&g_sin[s * 64 + d];
                    float2 ch = *(const float2*)&g_cos[(s + 8) * 64 + d];
                    float2 sh = *(const float2*)&g_sin[(s + 8) * 64 + d];

                    float x0 = acc[mt][nt][0],     x1 = acc[mt][nt][1];
                    float x2 = acc[mt][nt][2],     x3 = acc[mt][nt][3];
                    float y0 = acc[mt][nt + 4][0], y1 = acc[mt][nt + 4][1];
                    float y2 = acc[mt][nt + 4][2], y3 = acc[mt][nt + 4][3];

                    *(unsigned*)&dst[base_lo + d] =
                        packh2((x0 * cl.x - y0 * sl.x) * SC,
                               (x1 * cl.y - y1 * sl.y) * SC);
                    *(unsigned*)&dst[base_lo + d + 32] =
                        packh2((y0 * cl.x + x0 * sl.x) * SC,
                               (y1 * cl.y + x1 * sl.y) * SC);
                    *(unsigned*)&dst[base_hi + d] =
                        packh2((x2 * ch.x - y2 * sh.x) * SC,
                               (x3 * ch.y - y3 * sh.y) * SC);
                    *(unsigned*)&dst[base_hi + d + 32] =
                        packh2((y2 * ch.x + x2 * sh.x) * SC,
                               (y3 * ch.y + x3 * sh.y) * SC);
                }
            }
        }
    }
}

// ---------------- dense GEMM + bias (fp32 out) -------------------------------
__global__ __launch_bounds__(256, 2)
void gemm16_dense(const __half* __restrict__ A, const __half* __restrict__ Wt,
                  const float* __restrict__ bias, float* __restrict__ C) {
    extern __shared__ char dsm[];
    unsigned smem_base = (unsigned)__cvta_generic_to_shared(dsm);
    int tid = threadIdx.x, lane = tid & 31, warp = tid >> 5;
    int row0 = blockIdx.y * 128;
    int col0 = blockIdx.x * 128;
    int wm = (warp & 3) * 32;
    int wn = (warp >> 2) * 64;

    float acc[2][8][4];
    gemm16_main(A, Wt, row0, col0, smem_base, acc, tid, lane, wm, wn);

#pragma unroll
    for (int mt = 0; mt < 2; mt++) {
        int r = row0 + wm + mt * 16 + (lane >> 2);
#pragma unroll
        for (int nt = 0; nt < 8; nt++) {
            int c = col0 + wn + nt * 8 + 2 * (lane & 3);
            float bx = bias[c], by = bias[c + 1];
            float2 lo, hi;
            lo.x = acc[mt][nt][0] + bx; lo.y = acc[mt][nt][1] + by;
            hi.x = acc[mt][nt][2] + bx; hi.y = acc[mt][nt][3] + by;
            *(float2*)&C[(size_t)r * HID_ + c]       = lo;
            *(float2*)&C[(size_t)(r + 8) * HID_ + c] = hi;
        }
    }
}

// ---------------- causal flash attention (fp16 mma + ldmatrix) ---------------
// grid (8, 32): CTA x handles q-blocks {x, 15-x} -> uniform 34 k-tiles/CTA.
#define AROW 144
#define ABUF (64 * AROW)

__global__ __launch_bounds__(256, 2)
void attn16(__half* __restrict__ Out) {
    extern __shared__ char dsm[];
    unsigned smem_base = (unsigned)__cvta_generic_to_shared(dsm);
    unsigned kb_base = smem_base;
    unsigned vb_base = smem_base + 2 * ABUF;

    int bxi = blockIdx.x;                       // 0..7
    int bh  = blockIdx.y;
    int b = bh >> 4, h = bh & 15;

    const __half* Qb = g_q + (size_t)bh * S_ * HD_;
    const __half* Kb = g_k + (size_t)bh * S_ * HD_;
    const __half* Vb = g_v + (size_t)bh * S_ * HD_;

    int tid  = threadIdx.x;
    int lane = tid & 31;
    int warp = tid >> 5;

#pragma unroll 1
    for (int p = 0; p < 2; p++) {
        int qblk = p ? (15 - bxi) : bxi;
        int qb   = qblk * 128;
        int qt2  = qblk * 2;
        int row_lo = qb + warp * 16 + (lane >> 2);

        unsigned qf[4][4];
#pragma unroll
        for (int ks = 0; ks < 4; ks++) {
            const __half* qp = Qb + (size_t)row_lo * 64 + ks * 16 + 2 * (lane & 3);
            qf[ks][0] = *(const unsigned*)(qp);
            qf[ks][1] = *(const unsigned*)(qp + 8 * 64);
            qf[ks][2] = *(const unsigned*)(qp + 8);
            qf[ks][3] = *(const unsigned*)(qp + 8 * 64 + 8);
        }

        float o[8][4];
#pragma unroll
        for (int nt = 0; nt < 8; nt++)
#pragma unroll
            for (int j = 0; j < 4; j++) o[nt][j] = 0.0f;
        float m_lo = -1e30f, m_hi = -1e30f, l_lo = 0.0f, l_hi = 0.0f;

        auto load_kv = [&](int st, int kt) {
#pragma unroll
            for (int it = 0; it < 2; it++) {
                int id = tid + it * 256;
                int r = id >> 3, ch = id & 7;
                cp16s(kb_base + st * ABUF + r * AROW + ch * 16,
                      &Kb[(size_t)(kt * 64 + r) * 64 + ch * 8]);
                cp16s(vb_base + st * ABUF + r * AROW + ch * 16,
                      &Vb[(size_t)(kt * 64 + r) * 64 + ch * 8]);
            }
        };

        int nkt = qt2 + 2;
        load_kv(0, 0);
        CP_COMMIT;

        for (int kt = 0; kt < nkt; kt++) {
            int st = kt & 1;
            if (kt + 1 < nkt) { load_kv(st ^ 1, kt + 1); CP_COMMIT; CP_WAIT1; }
            else              { CP_WAIT0; }
            __syncthreads();

            if (kt * 64 <= qb + warp * 16 + 15) {
                unsigned kst = kb_base + st * ABUF;
                unsigned vst = vb_base + st * ABUF;

                float s[8][4];
#pragma unroll
                for (int nt = 0; nt < 8; nt++)
#pragma unroll
                    for (int j = 0; j < 4; j++) s[nt][j] = 0.0f;

#pragma unroll
                for (int ks = 0; ks < 4; ks++) {
#pragma unroll
                    for (int ntp = 0; ntp < 4; ntp++) {
                        int trow = ntp * 16 + (lane & 7) + ((lane >> 4) << 3);
                        unsigned addr = kst + trow * AROW + ks * 32
                                      + ((lane >> 3) & 1) * 16;
                        unsigned r[4];
                        ldsm_x4(r, addr);
                        mma_f16(s[2 * ntp],     qf[ks], r[0], r[1]);
                        mma_f16(s[2 * ntp + 1], qf[ks], r[2], r[3]);
                    }
                }

                if (kt >= qt2) {
#pragma unroll
                    for (int nt = 0; nt < 8; nt++) {
                        int key0 = kt * 64 + nt * 8 + 2 * (lane & 3);
                        if (key0     > row_lo)     s[nt][0] = -1e30f;
                        if (key0 + 1 > row_lo)     s[nt][1] = -1e30f;
                        if (key0     > row_lo + 8) s[nt][2] = -1e30f;
                        if (key0 + 1 > row_lo + 8) s[nt][3] = -1e30f;
                    }
                }

                float mloc_lo = -1e30f, mloc_hi = -1e30f;
#pragma unroll
                for (int nt = 0; nt < 8; nt++) {
                    mloc_lo = fmaxf(mloc_lo, fmaxf(s[nt][0], s[nt][1]));
                    mloc_hi = fmaxf(mloc_hi, fmaxf(s[nt][2], s[nt][3]));
                }
                mloc_lo = fmaxf(mloc_lo, __shfl_xor_sync(0xffffffffu, mloc_lo, 1));
                mloc_lo = fmaxf(mloc_lo, __shfl_xor_sync(0xffffffffu, mloc_lo, 2));
                mloc_hi = fmaxf(mloc_hi, __shfl_xor_sync(0xffffffffu, mloc_hi, 1));
                mloc_hi = fmaxf(mloc_hi, __shfl_xor_sync(0xffffffffu, mloc_hi, 2));

                float mn_lo = fmaxf(m_lo, mloc_lo);
                float mn_hi = fmaxf(m_hi, mloc_hi);
                float scl_lo = ex2(m_lo - mn_lo);
                float scl_hi = ex2(m_hi - mn_hi);
                m_lo = mn_lo; m_hi = mn_hi;

                float lloc_lo = 0.0f, lloc_hi = 0.0f;
#pragma unroll
                for (int nt = 0; nt < 8; nt++) {
                    s[nt][0] = ex2(s[nt][0] - m_lo);
                    s[nt][1] = ex2(s[nt][1] - m_lo);
                    s[nt][2] = ex2(s[nt][2] - m_hi);
                    s[nt][3] = ex2(s[nt][3] - m_hi);
                    lloc_lo += s[nt][0] + s[nt][1];
                    lloc_hi += s[nt][2] + s[nt][3];
                }
                lloc_lo += __shfl_xor_sync(0xffffffffu, lloc_lo, 1);
                lloc_lo += __shfl_xor_sync(0xffffffffu, lloc_lo, 2);
                lloc_hi += __shfl_xor_sync(0xffffffffu, lloc_hi, 1);
                lloc_hi += __shfl_xor_sync(0xffffffffu, lloc_hi, 2);
                l_lo = l_lo * scl_lo + lloc_lo;
                l_hi = l_hi * scl_hi + lloc_hi;

#pragma unroll
                for (int nt = 0; nt < 8; nt++) {
                    o[nt][0] *= scl_lo; o[nt][1] *= scl_lo;
                    o[nt][2] *= scl_hi; o[nt][3] *= scl_hi;
                }

#pragma unroll
                for (int ks = 0; ks < 4; ks++) {
                    unsigned pa[4];
                    pa[0] = packh2(s[2 * ks][0],     s[2 * ks][1]);
                    pa[1] = packh2(s[2 * ks][2],     s[2 * ks][3]);
                    pa[2] = packh2(s[2 * ks + 1][0], s[2 * ks + 1][1]);
                    pa[3] = packh2(s[2 * ks + 1][2], s[2 * ks + 1][3]);
#pragma unroll
                    for (int ntp = 0; ntp < 4; ntp++) {
                        int trow = ks * 16 + (lane & 7) + ((lane >> 3) & 1) * 8;
                        unsigned addr = vst + trow * AROW
                                      + (2 * ntp + (lane >> 4)) * 16;
                        unsigned r[4];
                        ldsm_x4_t(r, addr);
                        mma_f16(o[2 * ntp],     pa, r[0], r[1]);
                        mma_f16(o[2 * ntp + 1], pa, r[2], r[3]);
                    }
                }
            }
            __syncthreads();
        }

        float inv_lo = 1.0f / l_lo;
        float inv_hi = 1.0f / l_hi;
        size_t rb_lo = ((size_t)b * S_ + row_lo) * HID_;
        size_t rb_hi = ((size_t)b * S_ + row_lo + 8) * HID_;
#pragma unroll
        for (int nt = 0; nt < 8; nt++) {
            int col = h * 64 + nt * 8 + 2 * (lane & 3);
            *(unsigned*)&Out[rb_lo + col] =
                packh2(o[nt][0] * inv_lo, o[nt][1] * inv_lo);
            *(unsigned*)&Out[rb_hi + col] =
                packh2(o[nt][2] * inv_hi, o[nt][3] * inv_hi);
        }
    }
}

// ---------------- launch ----------------------------------------------------
extern "C" void kernel_launch(void* const* d_in, const int* in_sizes, int n_in,
                              void* d_out, int out_size) {
    const float* hidden  = (const float*)d_in[0];
    const float* w_qkv   = (const float*)d_in[1];
    const float* w_dense = (const float*)d_in[2];
    const float* b_dense = (const float*)d_in[3];
    float* out = (float*)d_out;

    void *p_attno, *p_hid, *p_wqkv, *p_wdense;
    cudaGetSymbolAddress(&p_attno, g_attno);
    cudaGetSymbolAddress(&p_hid, g_hid_h);
    cudaGetSymbolAddress(&p_wqkv, g_wqkv_t);
    cudaGetSymbolAddress(&p_wdense, g_wdense_t);

    rope_table_kernel<<<(S_ * HD_ + 255) / 256, 256>>>();

    f2h_kernel<<<(M_ * HID_ / 4 + 255) / 256, 256>>>(hidden, (__half*)p_hid,
                                                     M_ * HID_ / 4);
    {
        dim3 grid(QKV_N / 32, HID_ / 32);
        transpose_h_kernel<<<grid, dim3(32, 8)>>>(w_qkv, (__half*)p_wqkv,
                                                  HID_, QKV_N);
    }
    {
        dim3 grid(HID_ / 32, HID_ / 32);
        transpose_h_kernel<<<grid, dim3(32, 8)>>>(w_dense, (__half*)p_wdense,
                                                  HID_, HID_);
    }

    size_t gsmem = 4 * GBUF;   // 40960
    cudaFuncSetAttribute(gemm16_qkv, cudaFuncAttributeMaxDynamicSharedMemorySize,
                         (int)gsmem);
    cudaFuncSetAttribute(gemm16_dense, cudaFuncAttributeMaxDynamicSharedMemorySize,
                         (int)gsmem);

    // persistent QKV GEMM: 296 CTAs (2/SM), atomic ticket over 768 tiles
    gemm16_qkv<<<296, 256, gsmem>>>((const __half*)p_hid, (const __half*)p_wqkv);

    {
        size_t asmem = 4 * ABUF;   // 36864
        cudaFuncSetAttribute(attn16, cudaFuncAttributeMaxDynamicSharedMemorySize,
                             (int)asmem);
        dim3 grid(8, B_ * NH_);    // paired q-blocks: uniform 34 k-tiles/CTA
        attn16<<<grid, 256, asmem>>>((__half*)p_attno);
    }

    {
        dim3 grid(HID_ / 128, M_ / 128);
        gemm16_dense<<<grid, 256, gsmem>>>((const __half*)p_attno,
                                           (const __half*)p_wdense, b_dense, out);
    }
}